// round 11
// baseline (speedup 1.0000x reference)
#include <cuda_runtime.h>
#include <cuda_bf16.h>
#include <math.h>
#include <stdint.h>

#define N_NODES 100000
#define N_EDGES 1600000
#define IN_F    16
#define HID     100
#define OUTF    3

// A' smem: hi section [0,208) + lo section [208,416), row stride 424 bf16
#define SEC    208
#define NKF    39          // B gmem image: 3 sections x 13 kf (hi, hi, lo)
#define MT     64
#define THR    256         // 8 warps: 4 along M x 2 along N
#define A_STR  424
#define SA_BYTES (MT * A_STR * 2)       // 54272
#define SB_BYTES (13 * 4096)            // 53248 (one 13-kf phase of B)
#define SMEM_TOT (SA_BYTES + SB_BYTES)  // 107520 -> 2 CTAs/SM

#define SCAN_B 1024
#define NBLK   ((N_NODES + SCAN_B - 1) / SCAN_B)   // 98

// ---------------------------------------------------------------------------
// Scratch (device globals; allocation APIs are forbidden)
// ---------------------------------------------------------------------------
__device__ __align__(16) float g_h  [N_NODES * HID];
__device__ __align__(16) float g_h2 [N_NODES * HID];
__device__ __align__(16) float g_red[N_NODES * HID];
__device__ __align__(16) uint4 g_Bfrag[3 * NKF * 2 * 4 * 32];
// CSR scratch
__device__ int   g_cnt   [N_NODES];
__device__ int   g_rowptr[N_NODES + 1];
__device__ int   g_cur   [N_NODES];
__device__ int   g_bsum  [NBLK];
__device__ int   g_bsumex[NBLK];
__device__ __align__(16) uint2 g_edge[N_EDGES];   // {src, w bits} sorted by dst

__device__ __forceinline__ uint32_t smem_u32(const void* p) {
    uint32_t a;
    asm("{ .reg .u64 t; cvta.to.shared.u64 t, %1; cvt.u32.u64 %0, t; }" : "=r"(a) : "l"(p));
    return a;
}
__device__ __forceinline__ uint32_t bf2_u32(__nv_bfloat162 v) {
    return *reinterpret_cast<uint32_t*>(&v);
}

#define LDSM4(r, addr)                                                           \
    asm volatile("ldmatrix.sync.aligned.m8n8.x4.shared.b16 {%0,%1,%2,%3}, [%4];" \
                 : "=r"((r)[0]), "=r"((r)[1]), "=r"((r)[2]), "=r"((r)[3])        \
                 : "r"(addr))

#define MMA16816(acc, a, bx, by)                                                 \
    asm volatile("mma.sync.aligned.m16n8k16.row.col.f32.bf16.bf16.f32 "          \
                 "{%0,%1,%2,%3}, {%4,%5,%6,%7}, {%8,%9}, {%0,%1,%2,%3};"         \
                 : "+f"((acc)[0]), "+f"((acc)[1]), "+f"((acc)[2]), "+f"((acc)[3])\
                 : "r"((a)[0]), "r"((a)[1]), "r"((a)[2]), "r"((a)[3]),           \
                   "r"(bx), "r"(by))

#define CP_ASYNC16(dst, src)                                                     \
    asm volatile("cp.async.cg.shared.global [%0], [%1], 16;"                     \
                 :: "r"(dst), "l"(src) : "memory")

// ---------------------------------------------------------------------------
// CSR build
// ---------------------------------------------------------------------------
__global__ __launch_bounds__(256)
void hist_kernel(const int* __restrict__ dst) {
    int e = blockIdx.x * 256 + threadIdx.x;
    if (e < N_EDGES) atomicAdd(&g_cnt[dst[e]], 1);
}

__global__ __launch_bounds__(SCAN_B)
void block_sum_kernel() {
    __shared__ int s[SCAN_B];
    int i = blockIdx.x * SCAN_B + threadIdx.x;
    s[threadIdx.x] = (i < N_NODES) ? g_cnt[i] : 0;
    __syncthreads();
    for (int st = SCAN_B / 2; st > 0; st >>= 1) {
        if (threadIdx.x < st) s[threadIdx.x] += s[threadIdx.x + st];
        __syncthreads();
    }
    if (threadIdx.x == 0) g_bsum[blockIdx.x] = s[0];
}

__global__ __launch_bounds__(128)
void scan_bsum_kernel() {
    __shared__ int s[128];
    int t = threadIdx.x;
    int c = (t < NBLK) ? g_bsum[t] : 0;
    s[t] = c;
    __syncthreads();
    for (int st = 1; st < 128; st <<= 1) {
        int v = (t >= st) ? s[t - st] : 0;
        __syncthreads();
        s[t] += v;
        __syncthreads();
    }
    if (t < NBLK) g_bsumex[t] = s[t] - c;   // exclusive
}

__global__ __launch_bounds__(SCAN_B)
void rowptr_kernel() {
    __shared__ int s[SCAN_B];
    int i = blockIdx.x * SCAN_B + threadIdx.x;
    int c = (i < N_NODES) ? g_cnt[i] : 0;
    s[threadIdx.x] = c;
    __syncthreads();
    for (int st = 1; st < SCAN_B; st <<= 1) {
        int v = (threadIdx.x >= st) ? s[threadIdx.x - st] : 0;
        __syncthreads();
        s[threadIdx.x] += v;
        __syncthreads();
    }
    if (i < N_NODES) {
        int excl = g_bsumex[blockIdx.x] + s[threadIdx.x] - c;
        g_rowptr[i] = excl;
        g_cur[i]    = excl;
        if (i == N_NODES - 1) g_rowptr[N_NODES] = excl + c;
    }
}

__global__ __launch_bounds__(256)
void fill_kernel(const int* __restrict__ src, const int* __restrict__ dst,
                 const float* __restrict__ ef) {
    int e = blockIdx.x * 256 + threadIdx.x;
    if (e >= N_EDGES) return;
    int p = atomicAdd(&g_cur[dst[e]], 1);
    g_edge[p] = make_uint2((unsigned)src[e], __float_as_uint(ef[e]));
}

// ---------------------------------------------------------------------------
// Gather-reduce (CSR segment sum): red[n] = sum_e w_e * h[src_e]
// ---------------------------------------------------------------------------
__global__ __launch_bounds__(256)
void gather_kernel(const float* __restrict__ h, float* __restrict__ red) {
    const int wid  = threadIdx.x >> 5;
    const int lane = threadIdx.x & 31;
    const int n    = blockIdx.x * 8 + wid;
    if (n >= N_NODES) return;

    const int e0 = g_rowptr[n];
    const int e1 = g_rowptr[n + 1];
    float4 acc = make_float4(0.f, 0.f, 0.f, 0.f);

    int e = e0;
    for (; e + 2 <= e1; e += 2) {
        uint2 p0 = g_edge[e];
        uint2 p1 = g_edge[e + 1];
        float w0 = __uint_as_float(p0.y);
        float w1 = __uint_as_float(p1.y);
        if (lane < 25) {
            float4 v0 = *reinterpret_cast<const float4*>(h + (size_t)p0.x * HID + lane * 4);
            float4 v1 = *reinterpret_cast<const float4*>(h + (size_t)p1.x * HID + lane * 4);
            acc.x += w0 * v0.x + w1 * v1.x;
            acc.y += w0 * v0.y + w1 * v1.y;
            acc.z += w0 * v0.z + w1 * v1.z;
            acc.w += w0 * v0.w + w1 * v1.w;
        }
    }
    if (e < e1) {
        uint2 p0 = g_edge[e];
        float w0 = __uint_as_float(p0.y);
        if (lane < 25) {
            float4 v0 = *reinterpret_cast<const float4*>(h + (size_t)p0.x * HID + lane * 4);
            acc.x += w0 * v0.x; acc.y += w0 * v0.y;
            acc.z += w0 * v0.z; acc.w += w0 * v0.w;
        }
    }
    if (lane < 25)
        *reinterpret_cast<float4*>(red + (size_t)n * HID + lane * 4) = acc;
}

// ---------------------------------------------------------------------------
// Prep: pack B' (= W^T with hi/hi/lo sections) into MMA B-fragment layout.
// ---------------------------------------------------------------------------
__device__ __forceinline__ __nv_bfloat16 wconv(const float* W, int sec, int kk, int col) {
    float w = (kk < 2 * HID && col < HID) ? W[kk * HID + col] : 0.0f;
    __nv_bfloat16 hi = __float2bfloat16(w);
    return (sec == 2) ? __float2bfloat16(w - __bfloat162float(hi)) : hi;
}

__global__ __launch_bounds__(256)
void prep_B_kernel(const float* __restrict__ W1, const float* __restrict__ W2,
                   const float* __restrict__ W3)
{
    int i = blockIdx.x * 256 + threadIdx.x;
    if (i >= 3 * NKF * 2 * 4 * 32) return;
    int l    = i / (NKF * 256);
    int r    = i - l * (NKF * 256);
    int kf   = r >> 8;
    int r2   = r & 255;
    int wn   = r2 >> 7;
    int nbp  = (r2 >> 5) & 3;
    int lane = r2 & 31;

    int sec = kf / 13;
    int kk0 = (kf - sec * 13) * 16 + (lane & 3) * 2;
    int n0  = wn * 64 + (nbp * 2) * 8 + (lane >> 2);
    int n1  = n0 + 8;

    const float* W = (l == 0) ? W1 : (l == 1) ? W2 : W3;

    uint4 o;
    o.x = bf2_u32(__nv_bfloat162(wconv(W, sec, kk0,     n0), wconv(W, sec, kk0 + 1, n0)));
    o.y = bf2_u32(__nv_bfloat162(wconv(W, sec, kk0 + 8, n0), wconv(W, sec, kk0 + 9, n0)));
    o.z = bf2_u32(__nv_bfloat162(wconv(W, sec, kk0,     n1), wconv(W, sec, kk0 + 1, n1)));
    o.w = bf2_u32(__nv_bfloat162(wconv(W, sec, kk0 + 8, n1), wconv(W, sec, kk0 + 9, n1)));
    g_Bfrag[i] = o;
}

// ---------------------------------------------------------------------------
// MPL GEMM: out[n,0:100] = relu( concat(h[n], red[n]) @ W + b )
// B staged in smem per 13-kf phase via cp.async (overlapped with A-fill /
// co-resident CTA's compute). Mainloop: pure LDS + MMA, zero gmem.
// Phase 1: B_hi x (A_hi then A_lo); Phase 2: B_lo x A_hi. 3 syncs/CTA.
// ---------------------------------------------------------------------------
__global__ __launch_bounds__(THR, 2)
void mpl_gemm_mma(const float* __restrict__ h,
                  const float* __restrict__ red,
                  const uint4* __restrict__ Bf,   // layer base in g_Bfrag
                  const float* __restrict__ b,
                  float* __restrict__ out,
                  int n_nodes)
{
    extern __shared__ __align__(16) uint8_t smem[];
    __nv_bfloat16* sA = reinterpret_cast<__nv_bfloat16*>(smem);
    const uint32_t sbase = smem_u32(smem);
    const uint32_t sbB   = sbase + SA_BYTES;

    const int tid    = threadIdx.x;
    const int wid    = tid >> 5;
    const int lane   = tid & 31;
    const int warp_m = wid >> 1;         // 0..3
    const int warp_n = wid & 1;          // 0..1
    const int node0  = blockIdx.x * MT;
    const char* bgm  = reinterpret_cast<const char*>(Bf);

    // ---- stage B_hi (kf 0..12, 53KB) via cp.async; overlaps A-fill ----
    {
        const char* src = bgm + tid * 16;
        uint32_t dst = sbB + (uint32_t)(tid * 16);
#pragma unroll
        for (int it = 0; it < 13; ++it)
            CP_ASYNC16(dst + (uint32_t)(it * 4096), src + it * 4096);
        asm volatile("cp.async.commit_group;" ::: "memory");
    }

    // ---- fill A' once: hi at [0,208), lo at [208,416) ----
    for (int i = tid; i < MT * 52; i += THR) {
        int row = i / 52;
        int kk  = (i - row * 52) * 4;
        int n   = node0 + row;
        float4 v = make_float4(0.f, 0.f, 0.f, 0.f);
        if (n < n_nodes) {
            if (kk < HID)          v = *reinterpret_cast<const float4*>(h + (size_t)n * HID + kk);
            else if (kk < 2 * HID) v = *reinterpret_cast<const float4*>(red + (size_t)n * HID + kk - HID);
        }
        __nv_bfloat162 h0 = __floats2bfloat162_rn(v.x, v.y);
        __nv_bfloat162 h1 = __floats2bfloat162_rn(v.z, v.w);
        __nv_bfloat162 l0 = __floats2bfloat162_rn(v.x - __bfloat162float(h0.x),
                                                  v.y - __bfloat162float(h0.y));
        __nv_bfloat162 l1 = __floats2bfloat162_rn(v.z - __bfloat162float(h1.x),
                                                  v.w - __bfloat162float(h1.y));
        __nv_bfloat16* rp = sA + row * A_STR;
        *reinterpret_cast<uint2*>(rp + kk)       = make_uint2(bf2_u32(h0), bf2_u32(h1));
        *reinterpret_cast<uint2*>(rp + SEC + kk) = make_uint2(bf2_u32(l0), bf2_u32(l1));
    }
    asm volatile("cp.async.wait_group 0;" ::: "memory");
    __syncthreads();

    float acc[8][4];
#pragma unroll
    for (int f = 0; f < 8; ++f)
#pragma unroll
        for (int j = 0; j < 4; ++j) acc[f][j] = 0.0f;

    const int lrow  = lane & 15;
    const int lkoff = (lane >> 4) << 3;
    const uint32_t aHi = sbase + (uint32_t)(((warp_m * 16 + lrow) * A_STR + lkoff) * 2);
    const uint32_t aLo = aHi + SEC * 2;
    // smem B fragment pointer: element index kf*256 + warp_n*128 + nbp*32 + lane
    const uint4* bsm = reinterpret_cast<const uint4*>(smem + SA_BYTES) + warp_n * 128 + lane;

    uint32_t ah[2][4], al[2][4];
    uint4 bb[2][4];

    // ================= Phase 1: B_hi x (A_hi + A_lo) =================
    LDSM4(ah[0], aHi);
    LDSM4(al[0], aLo);
#pragma unroll
    for (int nbp = 0; nbp < 4; ++nbp) bb[0][nbp] = bsm[nbp * 32];
#pragma unroll
    for (int k = 0; k < 13; ++k) {
        const int cur = k & 1, nxt = cur ^ 1;
        if (k + 1 < 13) {
            LDSM4(ah[nxt], aHi + (uint32_t)((k + 1) * 32));
            LDSM4(al[nxt], aLo + (uint32_t)((k + 1) * 32));
#pragma unroll
            for (int nbp = 0; nbp < 4; ++nbp)
                bb[nxt][nbp] = bsm[(k + 1) * 256 + nbp * 32];
        }
#pragma unroll
        for (int nbp = 0; nbp < 4; ++nbp) {
            const uint4 bv = bb[cur][nbp];
            MMA16816(acc[nbp * 2],     ah[cur], bv.x, bv.y);
            MMA16816(acc[nbp * 2 + 1], ah[cur], bv.z, bv.w);
        }
#pragma unroll
        for (int nbp = 0; nbp < 4; ++nbp) {
            const uint4 bv = bb[cur][nbp];
            MMA16816(acc[nbp * 2],     al[cur], bv.x, bv.y);
            MMA16816(acc[nbp * 2 + 1], al[cur], bv.z, bv.w);
        }
    }

    // ---- swap in B_lo (kf 26..38) ----
    __syncthreads();   // everyone done reading B_hi
    {
        const char* src = bgm + 26 * 4096 + tid * 16;
        uint32_t dst = sbB + (uint32_t)(tid * 16);
#pragma unroll
        for (int it = 0; it < 13; ++it)
            CP_ASYNC16(dst + (uint32_t)(it * 4096), src + it * 4096);
        asm volatile("cp.async.commit_group;" ::: "memory");
        asm volatile("cp.async.wait_group 0;" ::: "memory");
    }
    __syncthreads();

    // ================= Phase 2: B_lo x A_hi =================
    LDSM4(ah[0], aHi);
#pragma unroll
    for (int nbp = 0; nbp < 4; ++nbp) bb[0][nbp] = bsm[nbp * 32];
#pragma unroll
    for (int k = 0; k < 13; ++k) {
        const int cur = k & 1, nxt = cur ^ 1;
        if (k + 1 < 13) {
            LDSM4(ah[nxt], aHi + (uint32_t)((k + 1) * 32));
#pragma unroll
            for (int nbp = 0; nbp < 4; ++nbp)
                bb[nxt][nbp] = bsm[(k + 1) * 256 + nbp * 32];
        }
#pragma unroll
        for (int nbp = 0; nbp < 4; ++nbp) {
            const uint4 bv = bb[cur][nbp];
            MMA16816(acc[nbp * 2],     ah[cur], bv.x, bv.y);
            MMA16816(acc[nbp * 2 + 1], ah[cur], bv.z, bv.w);
        }
    }

    // ---- epilogue: bias + relu + float2 stores ----
    const int gr = lane >> 2;
    const int tc = lane & 3;
    const int r0 = node0 + warp_m * 16 + gr;
    const int r1 = r0 + 8;
#pragma unroll
    for (int f = 0; f < 8; ++f) {
        int col = warp_n * 64 + f * 8 + tc * 2;
        if (col < HID) {
            float b0 = b[col], b1 = b[col + 1];
            if (r0 < n_nodes) {
                float2 v;
                v.x = fmaxf(acc[f][0] + b0, 0.f);
                v.y = fmaxf(acc[f][1] + b1, 0.f);
                *reinterpret_cast<float2*>(out + (size_t)r0 * HID + col) = v;
            }
            if (r1 < n_nodes) {
                float2 v;
                v.x = fmaxf(acc[f][2] + b0, 0.f);
                v.y = fmaxf(acc[f][3] + b1, 0.f);
                *reinterpret_cast<float2*>(out + (size_t)r1 * HID + col) = v;
            }
        }
    }
}

// ---------------------------------------------------------------------------
// Lift GEMM (FFMA; tiny K=16): h = tanh(x @ W_lift + b_lift)
// ---------------------------------------------------------------------------
template <int KDIM>
__global__ __launch_bounds__(512, 1)
void lift_gemm_kernel(const float* __restrict__ in1,
                      const float* __restrict__ W,
                      const float* __restrict__ b,
                      float* __restrict__ out,
                      int n_nodes)
{
    extern __shared__ float sm[];
    constexpr int SSTR = KDIM + 4;
    float* sW  = sm;
    float* sIn = sm + KDIM * 128;

    const int tid   = threadIdx.x;
    const int node0 = blockIdx.x * 128;

    for (int i = tid; i < KDIM * 128; i += 512) {
        int k = i >> 7, c = i & 127;
        sW[i] = (c < HID) ? W[k * HID + c] : 0.0f;
    }
    for (int i = tid; i < 128 * KDIM; i += 512) {
        int nl = i / KDIM, k = i - nl * KDIM;
        int n  = node0 + nl;
        sIn[nl * SSTR + k] = (n < n_nodes) ? in1[n * KDIM + k] : 0.0f;
    }
    __syncthreads();

    const int lane = tid & 31;
    const int wp   = tid >> 5;
    const float* abase = sIn + wp * 8 * SSTR;
    const float* wbase = sW + lane * 4;

    float4 acc[8];
#pragma unroll
    for (int j = 0; j < 8; ++j) acc[j] = make_float4(0.f, 0.f, 0.f, 0.f);

#pragma unroll
    for (int k0 = 0; k0 < KDIM; k0 += 4) {
        const float4 w0 = *reinterpret_cast<const float4*>(wbase + (k0 + 0) * 128);
        const float4 w1 = *reinterpret_cast<const float4*>(wbase + (k0 + 1) * 128);
        const float4 w2 = *reinterpret_cast<const float4*>(wbase + (k0 + 2) * 128);
        const float4 w3 = *reinterpret_cast<const float4*>(wbase + (k0 + 3) * 128);
#pragma unroll
        for (int j = 0; j < 8; ++j) {
            const float4 a = *reinterpret_cast<const float4*>(abase + j * SSTR + k0);
            acc[j].x += a.x * w0.x; acc[j].y += a.x * w0.y; acc[j].z += a.x * w0.z; acc[j].w += a.x * w0.w;
            acc[j].x += a.y * w1.x; acc[j].y += a.y * w1.y; acc[j].z += a.y * w1.z; acc[j].w += a.y * w1.w;
            acc[j].x += a.z * w2.x; acc[j].y += a.z * w2.y; acc[j].z += a.z * w2.z; acc[j].w += a.z * w2.w;
            acc[j].x += a.w * w3.x; acc[j].y += a.w * w3.y; acc[j].z += a.w * w3.z; acc[j].w += a.w * w3.w;
        }
    }

    if (lane < 25) {
        const float4 bias = *reinterpret_cast<const float4*>(b + lane * 4);
#pragma unroll
        for (int j = 0; j < 8; ++j) {
            int n = node0 + wp * 8 + j;
            if (n < n_nodes) {
                float4 r;
                r.x = tanhf(acc[j].x + bias.x); r.y = tanhf(acc[j].y + bias.y);
                r.z = tanhf(acc[j].z + bias.z); r.w = tanhf(acc[j].w + bias.w);
                *reinterpret_cast<float4*>(out + (size_t)n * HID + lane * 4) = r;
            }
        }
    }
}

// ---------------------------------------------------------------------------
// Output head: y[n] = sigmoid(h[n,0:100] @ W_out[100x3] + b_out)
// ---------------------------------------------------------------------------
__global__ __launch_bounds__(256)
void out_kernel(const float* __restrict__ h,
                const float* __restrict__ Wo,
                const float* __restrict__ bo,
                float* __restrict__ y,
                int n_nodes)
{
    __shared__ float sW[HID * OUTF];
    int tid = threadIdx.x;
    for (int i = tid; i < HID * OUTF; i += 256) sW[i] = Wo[i];
    __syncthreads();

    int node = blockIdx.x * 256 + tid;
    if (node >= n_nodes) return;

    float a0 = bo[0], a1 = bo[1], a2 = bo[2];
    const float4* hv = reinterpret_cast<const float4*>(h + (size_t)node * HID);
#pragma unroll
    for (int kb = 0; kb < 25; ++kb) {
        float4 v = hv[kb];
        int k = kb * 4;
        a0 += v.x * sW[(k+0)*3+0]; a1 += v.x * sW[(k+0)*3+1]; a2 += v.x * sW[(k+0)*3+2];
        a0 += v.y * sW[(k+1)*3+0]; a1 += v.y * sW[(k+1)*3+1]; a2 += v.y * sW[(k+1)*3+2];
        a0 += v.z * sW[(k+2)*3+0]; a1 += v.z * sW[(k+2)*3+1]; a2 += v.z * sW[(k+2)*3+2];
        a0 += v.w * sW[(k+3)*3+0]; a1 += v.w * sW[(k+3)*3+1]; a2 += v.w * sW[(k+3)*3+2];
    }
    y[(size_t)node * 3 + 0] = 1.0f / (1.0f + expf(-a0));
    y[(size_t)node * 3 + 1] = 1.0f / (1.0f + expf(-a1));
    y[(size_t)node * 3 + 2] = 1.0f / (1.0f + expf(-a2));
}

// ---------------------------------------------------------------------------
extern "C" void kernel_launch(void* const* d_in, const int* in_sizes, int n_in,
                              void* d_out, int out_size)
{
    const float* x      = (const float*)d_in[0];
    const float* ef     = (const float*)d_in[1];
    const int*   src    = (const int*)  d_in[2];
    const int*   dst    = (const int*)  d_in[3];
    const float* W_lift = (const float*)d_in[4];
    const float* b_lift = (const float*)d_in[5];
    const float* W1     = (const float*)d_in[6];
    const float* b1     = (const float*)d_in[7];
    const float* W2     = (const float*)d_in[8];
    const float* b2     = (const float*)d_in[9];
    const float* W3     = (const float*)d_in[10];
    const float* b3     = (const float*)d_in[11];
    const float* W_out  = (const float*)d_in[12];
    const float* b_out  = (const float*)d_in[13];
    float* y = (float*)d_out;

    float *h, *h2, *red;
    uint4* Bf;
    int* cnt;
    cudaGetSymbolAddress((void**)&h,   g_h);
    cudaGetSymbolAddress((void**)&h2,  g_h2);
    cudaGetSymbolAddress((void**)&red, g_red);
    cudaGetSymbolAddress((void**)&Bf,  g_Bfrag);
    cudaGetSymbolAddress((void**)&cnt, g_cnt);

    const size_t SMEM_LIFT = (IN_F * 128 + 128 * (IN_F + 4)) * sizeof(float);

    cudaFuncSetAttribute((const void*)mpl_gemm_mma,
                         cudaFuncAttributeMaxDynamicSharedMemorySize, SMEM_TOT);

    // 0) weight prep + CSR build (once per launch)
    prep_B_kernel<<<(3 * NKF * 256 + 255) / 256, 256>>>(W1, W2, W3);
    cudaMemsetAsync(cnt, 0, N_NODES * sizeof(int));
    hist_kernel<<<(N_EDGES + 255) / 256, 256>>>(dst);
    block_sum_kernel<<<NBLK, SCAN_B>>>();
    scan_bsum_kernel<<<1, 128>>>();
    rowptr_kernel<<<NBLK, SCAN_B>>>();
    fill_kernel<<<(N_EDGES + 255) / 256, 256>>>(src, dst, ef);

    // 1) lift
    lift_gemm_kernel<IN_F><<<(N_NODES + 127) / 128, 512, SMEM_LIFT>>>(
        x, W_lift, b_lift, h, N_NODES);

    const int MPL_GRID    = (N_NODES + MT - 1) / MT;   // 1563
    const int GATHER_GRID = (N_NODES + 7) / 8;          // 12500

    const float* bs[3] = { b1, b2, b3 };
    float* bufs[4] = { h, h2, h, h2 };

    for (int l = 0; l < 3; ++l) {
        float* hin  = bufs[l];
        float* hout = bufs[l + 1];
        gather_kernel<<<GATHER_GRID, 256>>>(hin, red);
        mpl_gemm_mma<<<MPL_GRID, THR, SMEM_TOT>>>(
            hin, red, Bf + (size_t)l * NKF * 256, bs[l], hout, N_NODES);
    }

    // 3) output head
    out_kernel<<<(N_NODES + 255) / 256, 256>>>(h2, W_out, b_out, y, N_NODES);

    (void)in_sizes; (void)n_in; (void)out_size;
}

// round 12
// speedup vs baseline: 1.0478x; 1.0478x over previous
#include <cuda_runtime.h>
#include <cuda_bf16.h>
#include <math.h>
#include <stdint.h>

#define N_NODES 100000
#define N_EDGES 1600000
#define IN_F    16
#define HID     100
#define OUTF    3

// A' smem: hi section [0,208) + lo section [208,416), row stride 424 bf16
#define SEC    208
#define MT     80
#define THR    320         // 10 warps: 5 along M x 2 along N
#define A_STR  424
#define SA_BYTES (MT * A_STR * 2)   // 81408

// B image: [kf(39 = 3 sections x 13)][unit(7 n16-units)][lane(32)] uint4
// warp_n=0 -> units 0..3 (cols 0..63), warp_n=1 -> units 4..6 (cols 64..111)
#define NKF    39
#define NUNIT  7
#define KF_STRIDE (NUNIT * 32)      // uint4 elements per kf = 224

#define SCAN_B 1024
#define NBLK   ((N_NODES + SCAN_B - 1) / SCAN_B)   // 98

// ---------------------------------------------------------------------------
// Scratch (device globals; allocation APIs are forbidden)
// ---------------------------------------------------------------------------
__device__ __align__(16) float g_h  [N_NODES * HID];
__device__ __align__(16) float g_h2 [N_NODES * HID];
__device__ __align__(16) float g_red[N_NODES * HID];
__device__ __align__(16) uint4 g_Bfrag[3 * NKF * KF_STRIDE];   // 3 x 8736
// CSR scratch
__device__ int   g_cnt   [N_NODES];
__device__ int   g_rowptr[N_NODES + 1];
__device__ int   g_cur   [N_NODES];
__device__ int   g_bsum  [NBLK];
__device__ int   g_bsumex[NBLK];
__device__ __align__(16) uint2 g_edge[N_EDGES];   // {src, w bits} sorted by dst

__device__ __forceinline__ uint32_t smem_u32(const void* p) {
    uint32_t a;
    asm("{ .reg .u64 t; cvta.to.shared.u64 t, %1; cvt.u32.u64 %0, t; }" : "=r"(a) : "l"(p));
    return a;
}
__device__ __forceinline__ uint32_t bf2_u32(__nv_bfloat162 v) {
    return *reinterpret_cast<uint32_t*>(&v);
}

#define LDSM4(r, addr)                                                           \
    asm volatile("ldmatrix.sync.aligned.m8n8.x4.shared.b16 {%0,%1,%2,%3}, [%4];" \
                 : "=r"((r)[0]), "=r"((r)[1]), "=r"((r)[2]), "=r"((r)[3])        \
                 : "r"(addr))

#define MMA16816(acc, a, bx, by)                                                 \
    asm volatile("mma.sync.aligned.m16n8k16.row.col.f32.bf16.bf16.f32 "          \
                 "{%0,%1,%2,%3}, {%4,%5,%6,%7}, {%8,%9}, {%0,%1,%2,%3};"         \
                 : "+f"((acc)[0]), "+f"((acc)[1]), "+f"((acc)[2]), "+f"((acc)[3])\
                 : "r"((a)[0]), "r"((a)[1]), "r"((a)[2]), "r"((a)[3]),           \
                   "r"(bx), "r"(by))

// ---------------------------------------------------------------------------
// CSR build
// ---------------------------------------------------------------------------
__global__ __launch_bounds__(256)
void hist_kernel(const int* __restrict__ dst) {
    int e = blockIdx.x * 256 + threadIdx.x;
    if (e < N_EDGES) atomicAdd(&g_cnt[dst[e]], 1);
}

__global__ __launch_bounds__(SCAN_B)
void block_sum_kernel() {
    __shared__ int s[SCAN_B];
    int i = blockIdx.x * SCAN_B + threadIdx.x;
    s[threadIdx.x] = (i < N_NODES) ? g_cnt[i] : 0;
    __syncthreads();
    for (int st = SCAN_B / 2; st > 0; st >>= 1) {
        if (threadIdx.x < st) s[threadIdx.x] += s[threadIdx.x + st];
        __syncthreads();
    }
    if (threadIdx.x == 0) g_bsum[blockIdx.x] = s[0];
}

__global__ __launch_bounds__(128)
void scan_bsum_kernel() {
    __shared__ int s[128];
    int t = threadIdx.x;
    int c = (t < NBLK) ? g_bsum[t] : 0;
    s[t] = c;
    __syncthreads();
    for (int st = 1; st < 128; st <<= 1) {
        int v = (t >= st) ? s[t - st] : 0;
        __syncthreads();
        s[t] += v;
        __syncthreads();
    }
    if (t < NBLK) g_bsumex[t] = s[t] - c;   // exclusive
}

__global__ __launch_bounds__(SCAN_B)
void rowptr_kernel() {
    __shared__ int s[SCAN_B];
    int i = blockIdx.x * SCAN_B + threadIdx.x;
    int c = (i < N_NODES) ? g_cnt[i] : 0;
    s[threadIdx.x] = c;
    __syncthreads();
    for (int st = 1; st < SCAN_B; st <<= 1) {
        int v = (threadIdx.x >= st) ? s[threadIdx.x - st] : 0;
        __syncthreads();
        s[threadIdx.x] += v;
        __syncthreads();
    }
    if (i < N_NODES) {
        int excl = g_bsumex[blockIdx.x] + s[threadIdx.x] - c;
        g_rowptr[i] = excl;
        g_cur[i]    = excl;
        if (i == N_NODES - 1) g_rowptr[N_NODES] = excl + c;
    }
}

__global__ __launch_bounds__(256)
void fill_kernel(const int* __restrict__ src, const int* __restrict__ dst,
                 const float* __restrict__ ef) {
    int e = blockIdx.x * 256 + threadIdx.x;
    if (e >= N_EDGES) return;
    int p = atomicAdd(&g_cur[dst[e]], 1);
    g_edge[p] = make_uint2((unsigned)src[e], __float_as_uint(ef[e]));
}

// ---------------------------------------------------------------------------
// Gather-reduce (CSR segment sum): red[n] = sum_e w_e * h[src_e]
// ---------------------------------------------------------------------------
__global__ __launch_bounds__(256)
void gather_kernel(const float* __restrict__ h, float* __restrict__ red) {
    const int wid  = threadIdx.x >> 5;
    const int lane = threadIdx.x & 31;
    const int n    = blockIdx.x * 8 + wid;
    if (n >= N_NODES) return;

    const int e0 = g_rowptr[n];
    const int e1 = g_rowptr[n + 1];
    float4 acc = make_float4(0.f, 0.f, 0.f, 0.f);

    int e = e0;
    for (; e + 2 <= e1; e += 2) {
        uint2 p0 = g_edge[e];
        uint2 p1 = g_edge[e + 1];
        float w0 = __uint_as_float(p0.y);
        float w1 = __uint_as_float(p1.y);
        if (lane < 25) {
            float4 v0 = *reinterpret_cast<const float4*>(h + (size_t)p0.x * HID + lane * 4);
            float4 v1 = *reinterpret_cast<const float4*>(h + (size_t)p1.x * HID + lane * 4);
            acc.x += w0 * v0.x + w1 * v1.x;
            acc.y += w0 * v0.y + w1 * v1.y;
            acc.z += w0 * v0.z + w1 * v1.z;
            acc.w += w0 * v0.w + w1 * v1.w;
        }
    }
    if (e < e1) {
        uint2 p0 = g_edge[e];
        float w0 = __uint_as_float(p0.y);
        if (lane < 25) {
            float4 v0 = *reinterpret_cast<const float4*>(h + (size_t)p0.x * HID + lane * 4);
            acc.x += w0 * v0.x; acc.y += w0 * v0.y;
            acc.z += w0 * v0.z; acc.w += w0 * v0.w;
        }
    }
    if (lane < 25)
        *reinterpret_cast<float4*>(red + (size_t)n * HID + lane * 4) = acc;
}

// ---------------------------------------------------------------------------
// Prep: pack B' (= W^T with hi/hi/lo sections) into MMA B-fragment layout.
// New layout: [l][kf(39)][unit(7)][lane(32)] uint4, unit = n16 block.
// ---------------------------------------------------------------------------
__device__ __forceinline__ __nv_bfloat16 wconv(const float* W, int sec, int kk, int col) {
    float w = (kk < 2 * HID && col < HID) ? W[kk * HID + col] : 0.0f;
    __nv_bfloat16 hi = __float2bfloat16(w);
    return (sec == 2) ? __float2bfloat16(w - __bfloat162float(hi)) : hi;
}

__global__ __launch_bounds__(256)
void prep_B_kernel(const float* __restrict__ W1, const float* __restrict__ W2,
                   const float* __restrict__ W3)
{
    int i = blockIdx.x * 256 + threadIdx.x;
    if (i >= 3 * NKF * KF_STRIDE) return;
    int l    = i / (NKF * KF_STRIDE);
    int r    = i - l * (NKF * KF_STRIDE);
    int kf   = r / KF_STRIDE;
    int r2   = r - kf * KF_STRIDE;
    int unit = r2 >> 5;
    int lane = r2 & 31;

    int sec = kf / 13;
    int kk0 = (kf - sec * 13) * 16 + (lane & 3) * 2;
    int n0  = unit * 16 + (lane >> 2);
    int n1  = n0 + 8;

    const float* W = (l == 0) ? W1 : (l == 1) ? W2 : W3;

    uint4 o;
    o.x = bf2_u32(__nv_bfloat162(wconv(W, sec, kk0,     n0), wconv(W, sec, kk0 + 1, n0)));
    o.y = bf2_u32(__nv_bfloat162(wconv(W, sec, kk0 + 8, n0), wconv(W, sec, kk0 + 9, n0)));
    o.z = bf2_u32(__nv_bfloat162(wconv(W, sec, kk0,     n1), wconv(W, sec, kk0 + 1, n1)));
    o.w = bf2_u32(__nv_bfloat162(wconv(W, sec, kk0 + 8, n1), wconv(W, sec, kk0 + 9, n1)));
    g_Bfrag[i] = o;
}

// ---------------------------------------------------------------------------
// Mainloop phases (templated on units per warp). Round-8 structure:
// B via LDG.128 with distance-2 register prefetch, A via ldmatrix distance-1.
// ---------------------------------------------------------------------------
template <int NBPC>
__device__ __forceinline__ void phase_hi(float (*acc)[4], uint32_t aHi, uint32_t aLo,
                                         const uint4* __restrict__ bp)
{
    uint32_t ah[2][4], al[2][4];
    uint4 bb[2][NBPC];
    LDSM4(ah[0], aHi);
    LDSM4(al[0], aLo);
#pragma unroll
    for (int nbp = 0; nbp < NBPC; ++nbp) {
        bb[0][nbp] = bp[nbp * 32];
        bb[1][nbp] = bp[KF_STRIDE + nbp * 32];
    }
#pragma unroll
    for (int k = 0; k < 13; ++k) {
        const int cur = k & 1, nxt = cur ^ 1;
        if (k + 1 < 13) {
            LDSM4(ah[nxt], aHi + (uint32_t)((k + 1) * 32));
            LDSM4(al[nxt], aLo + (uint32_t)((k + 1) * 32));
        }
#pragma unroll
        for (int nbp = 0; nbp < NBPC; ++nbp) {
            const uint4 bv = bb[cur][nbp];
            MMA16816(acc[nbp * 2],     ah[cur], bv.x, bv.y);
            MMA16816(acc[nbp * 2 + 1], ah[cur], bv.z, bv.w);
            MMA16816(acc[nbp * 2],     al[cur], bv.x, bv.y);
            MMA16816(acc[nbp * 2 + 1], al[cur], bv.z, bv.w);
            if (k + 2 < 13) bb[cur][nbp] = bp[(k + 2) * KF_STRIDE + nbp * 32];
        }
    }
}

template <int NBPC>
__device__ __forceinline__ void phase_lo(float (*acc)[4], uint32_t aHi,
                                         const uint4* __restrict__ bp)
{
    uint32_t ah[2][4];
    uint4 bb[2][NBPC];
    LDSM4(ah[0], aHi);
#pragma unroll
    for (int nbp = 0; nbp < NBPC; ++nbp) {
        bb[0][nbp] = bp[nbp * 32];
        bb[1][nbp] = bp[KF_STRIDE + nbp * 32];
    }
#pragma unroll
    for (int k = 0; k < 13; ++k) {
        const int cur = k & 1, nxt = cur ^ 1;
        if (k + 1 < 13) LDSM4(ah[nxt], aHi + (uint32_t)((k + 1) * 32));
#pragma unroll
        for (int nbp = 0; nbp < NBPC; ++nbp) {
            const uint4 bv = bb[cur][nbp];
            MMA16816(acc[nbp * 2],     ah[cur], bv.x, bv.y);
            MMA16816(acc[nbp * 2 + 1], ah[cur], bv.z, bv.w);
            if (k + 2 < 13) bb[cur][nbp] = bp[(k + 2) * KF_STRIDE + nbp * 32];
        }
    }
}

// ---------------------------------------------------------------------------
// MPL GEMM: out[n,0:100] = relu( concat(h[n], red[n]) @ W + b )
// N = 112 (7 n16 units): warp_n=0 -> 4 units (cols 0..63), warp_n=1 -> 3 units
// (cols 64..111). 12.5% fewer MMAs than N=128.
// ---------------------------------------------------------------------------
__global__ __launch_bounds__(THR, 2)
void mpl_gemm_mma(const float* __restrict__ h,
                  const float* __restrict__ red,
                  const uint4* __restrict__ Bf,   // layer base in g_Bfrag
                  const float* __restrict__ b,
                  float* __restrict__ out,
                  int n_nodes)
{
    extern __shared__ __align__(16) uint8_t smem[];
    __nv_bfloat16* sA = reinterpret_cast<__nv_bfloat16*>(smem);
    const uint32_t sbase = smem_u32(smem);

    const int tid    = threadIdx.x;
    const int wid    = tid >> 5;
    const int lane   = tid & 31;
    const int warp_m = wid >> 1;         // 0..4
    const int warp_n = wid & 1;          // 0..1
    const int node0  = blockIdx.x * MT;

    // ---- fill A' once: hi at [0,208), lo at [208,416) ----
    for (int i = tid; i < MT * 52; i += THR) {
        int row = i / 52;
        int kk  = (i - row * 52) * 4;
        int n   = node0 + row;
        float4 v = make_float4(0.f, 0.f, 0.f, 0.f);
        if (n < n_nodes) {
            if (kk < HID)          v = *reinterpret_cast<const float4*>(h + (size_t)n * HID + kk);
            else if (kk < 2 * HID) v = *reinterpret_cast<const float4*>(red + (size_t)n * HID + kk - HID);
        }
        __nv_bfloat162 h0 = __floats2bfloat162_rn(v.x, v.y);
        __nv_bfloat162 h1 = __floats2bfloat162_rn(v.z, v.w);
        __nv_bfloat162 l0 = __floats2bfloat162_rn(v.x - __bfloat162float(h0.x),
                                                  v.y - __bfloat162float(h0.y));
        __nv_bfloat162 l1 = __floats2bfloat162_rn(v.z - __bfloat162float(h1.x),
                                                  v.w - __bfloat162float(h1.y));
        __nv_bfloat16* rp = sA + row * A_STR;
        *reinterpret_cast<uint2*>(rp + kk)       = make_uint2(bf2_u32(h0), bf2_u32(h1));
        *reinterpret_cast<uint2*>(rp + SEC + kk) = make_uint2(bf2_u32(l0), bf2_u32(l1));
    }
    __syncthreads();

    float acc[8][4];
#pragma unroll
    for (int f = 0; f < 8; ++f)
#pragma unroll
        for (int j = 0; j < 4; ++j) acc[f][j] = 0.0f;

    const int lrow  = lane & 15;
    const int lkoff = (lane >> 4) << 3;
    const uint32_t aHi = sbase + (uint32_t)(((warp_m * 16 + lrow) * A_STR + lkoff) * 2);
    const uint32_t aLo = aHi + SEC * 2;
    // warp's B pointer: units [warp_n*4 .. warp_n*4 + nbpc)
    const uint4* bp  = Bf + warp_n * 4 * 32 + lane;          // kf 0 (hi)
    const uint4* bp2 = bp + (size_t)26 * KF_STRIDE;          // kf 26 (lo)

    if (warp_n == 0) {
        phase_hi<4>(acc, aHi, aLo, bp);
        phase_lo<4>(acc, aHi, bp2);
    } else {
        phase_hi<3>(acc, aHi, aLo, bp);
        phase_lo<3>(acc, aHi, bp2);
    }

    // ---- epilogue: bias + relu + float2 stores ----
    const int gr = lane >> 2;
    const int tc = lane & 3;
    const int r0 = node0 + warp_m * 16 + gr;
    const int r1 = r0 + 8;
    const int nf = (warp_n == 0) ? 8 : 6;
#pragma unroll
    for (int f = 0; f < 8; ++f) {
        if (f >= nf) break;
        int col = warp_n * 64 + f * 8 + tc * 2;
        if (col < HID) {
            float b0 = b[col], b1 = b[col + 1];
            if (r0 < n_nodes) {
                float2 v;
                v.x = fmaxf(acc[f][0] + b0, 0.f);
                v.y = fmaxf(acc[f][1] + b1, 0.f);
                *reinterpret_cast<float2*>(out + (size_t)r0 * HID + col) = v;
            }
            if (r1 < n_nodes) {
                float2 v;
                v.x = fmaxf(acc[f][2] + b0, 0.f);
                v.y = fmaxf(acc[f][3] + b1, 0.f);
                *reinterpret_cast<float2*>(out + (size_t)r1 * HID + col) = v;
            }
        }
    }
}

// ---------------------------------------------------------------------------
// Lift GEMM (FFMA; tiny K=16): h = tanh(x @ W_lift + b_lift)
// ---------------------------------------------------------------------------
template <int KDIM>
__global__ __launch_bounds__(512, 1)
void lift_gemm_kernel(const float* __restrict__ in1,
                      const float* __restrict__ W,
                      const float* __restrict__ b,
                      float* __restrict__ out,
                      int n_nodes)
{
    extern __shared__ float sm[];
    constexpr int SSTR = KDIM + 4;
    float* sW  = sm;
    float* sIn = sm + KDIM * 128;

    const int tid   = threadIdx.x;
    const int node0 = blockIdx.x * 128;

    for (int i = tid; i < KDIM * 128; i += 512) {
        int k = i >> 7, c = i & 127;
        sW[i] = (c < HID) ? W[k * HID + c] : 0.0f;
    }
    for (int i = tid; i < 128 * KDIM; i += 512) {
        int nl = i / KDIM, k = i - nl * KDIM;
        int n  = node0 + nl;
        sIn[nl * SSTR + k] = (n < n_nodes) ? in1[n * KDIM + k] : 0.0f;
    }
    __syncthreads();

    const int lane = tid & 31;
    const int wp   = tid >> 5;
    const float* abase = sIn + wp * 8 * SSTR;
    const float* wbase = sW + lane * 4;

    float4 acc[8];
#pragma unroll
    for (int j = 0; j < 8; ++j) acc[j] = make_float4(0.f, 0.f, 0.f, 0.f);

#pragma unroll
    for (int k0 = 0; k0 < KDIM; k0 += 4) {
        const float4 w0 = *reinterpret_cast<const float4*>(wbase + (k0 + 0) * 128);
        const float4 w1 = *reinterpret_cast<const float4*>(wbase + (k0 + 1) * 128);
        const float4 w2 = *reinterpret_cast<const float4*>(wbase + (k0 + 2) * 128);
        const float4 w3 = *reinterpret_cast<const float4*>(wbase + (k0 + 3) * 128);
#pragma unroll
        for (int j = 0; j < 8; ++j) {
            const float4 a = *reinterpret_cast<const float4*>(abase + j * SSTR + k0);
            acc[j].x += a.x * w0.x; acc[j].y += a.x * w0.y; acc[j].z += a.x * w0.z; acc[j].w += a.x * w0.w;
            acc[j].x += a.y * w1.x; acc[j].y += a.y * w1.y; acc[j].z += a.y * w1.z; acc[j].w += a.y * w1.w;
            acc[j].x += a.z * w2.x; acc[j].y += a.z * w2.y; acc[j].z += a.z * w2.z; acc[j].w += a.z * w2.w;
            acc[j].x += a.w * w3.x; acc[j].y += a.w * w3.y; acc[j].z += a.w * w3.z; acc[j].w += a.w * w3.w;
        }
    }

    if (lane < 25) {
        const float4 bias = *reinterpret_cast<const float4*>(b + lane * 4);
#pragma unroll
        for (int j = 0; j < 8; ++j) {
            int n = node0 + wp * 8 + j;
            if (n < n_nodes) {
                float4 r;
                r.x = tanhf(acc[j].x + bias.x); r.y = tanhf(acc[j].y + bias.y);
                r.z = tanhf(acc[j].z + bias.z); r.w = tanhf(acc[j].w + bias.w);
                *reinterpret_cast<float4*>(out + (size_t)n * HID + lane * 4) = r;
            }
        }
    }
}

// ---------------------------------------------------------------------------
// Output head: y[n] = sigmoid(h[n,0:100] @ W_out[100x3] + b_out)
// ---------------------------------------------------------------------------
__global__ __launch_bounds__(256)
void out_kernel(const float* __restrict__ h,
                const float* __restrict__ Wo,
                const float* __restrict__ bo,
                float* __restrict__ y,
                int n_nodes)
{
    __shared__ float sW[HID * OUTF];
    int tid = threadIdx.x;
    for (int i = tid; i < HID * OUTF; i += 256) sW[i] = Wo[i];
    __syncthreads();

    int node = blockIdx.x * 256 + tid;
    if (node >= n_nodes) return;

    float a0 = bo[0], a1 = bo[1], a2 = bo[2];
    const float4* hv = reinterpret_cast<const float4*>(h + (size_t)node * HID);
#pragma unroll
    for (int kb = 0; kb < 25; ++kb) {
        float4 v = hv[kb];
        int k = kb * 4;
        a0 += v.x * sW[(k+0)*3+0]; a1 += v.x * sW[(k+0)*3+1]; a2 += v.x * sW[(k+0)*3+2];
        a0 += v.y * sW[(k+1)*3+0]; a1 += v.y * sW[(k+1)*3+1]; a2 += v.y * sW[(k+1)*3+2];
        a0 += v.z * sW[(k+2)*3+0]; a1 += v.z * sW[(k+2)*3+1]; a2 += v.z * sW[(k+2)*3+2];
        a0 += v.w * sW[(k+3)*3+0]; a1 += v.w * sW[(k+3)*3+1]; a2 += v.w * sW[(k+3)*3+2];
    }
    y[(size_t)node * 3 + 0] = 1.0f / (1.0f + expf(-a0));
    y[(size_t)node * 3 + 1] = 1.0f / (1.0f + expf(-a1));
    y[(size_t)node * 3 + 2] = 1.0f / (1.0f + expf(-a2));
}

// ---------------------------------------------------------------------------
extern "C" void kernel_launch(void* const* d_in, const int* in_sizes, int n_in,
                              void* d_out, int out_size)
{
    const float* x      = (const float*)d_in[0];
    const float* ef     = (const float*)d_in[1];
    const int*   src    = (const int*)  d_in[2];
    const int*   dst    = (const int*)  d_in[3];
    const float* W_lift = (const float*)d_in[4];
    const float* b_lift = (const float*)d_in[5];
    const float* W1     = (const float*)d_in[6];
    const float* b1     = (const float*)d_in[7];
    const float* W2     = (const float*)d_in[8];
    const float* b2     = (const float*)d_in[9];
    const float* W3     = (const float*)d_in[10];
    const float* b3     = (const float*)d_in[11];
    const float* W_out  = (const float*)d_in[12];
    const float* b_out  = (const float*)d_in[13];
    float* y = (float*)d_out;

    float *h, *h2, *red;
    uint4* Bf;
    int* cnt;
    cudaGetSymbolAddress((void**)&h,   g_h);
    cudaGetSymbolAddress((void**)&h2,  g_h2);
    cudaGetSymbolAddress((void**)&red, g_red);
    cudaGetSymbolAddress((void**)&Bf,  g_Bfrag);
    cudaGetSymbolAddress((void**)&cnt, g_cnt);

    const size_t SMEM_LIFT = (IN_F * 128 + 128 * (IN_F + 4)) * sizeof(float);

    cudaFuncSetAttribute((const void*)mpl_gemm_mma,
                         cudaFuncAttributeMaxDynamicSharedMemorySize, SA_BYTES);

    // 0) weight prep + CSR build (once per launch)
    prep_B_kernel<<<(3 * NKF * KF_STRIDE + 255) / 256, 256>>>(W1, W2, W3);
    cudaMemsetAsync(cnt, 0, N_NODES * sizeof(int));
    hist_kernel<<<(N_EDGES + 255) / 256, 256>>>(dst);
    block_sum_kernel<<<NBLK, SCAN_B>>>();
    scan_bsum_kernel<<<1, 128>>>();
    rowptr_kernel<<<NBLK, SCAN_B>>>();
    fill_kernel<<<(N_EDGES + 255) / 256, 256>>>(src, dst, ef);

    // 1) lift
    lift_gemm_kernel<IN_F><<<(N_NODES + 127) / 128, 512, SMEM_LIFT>>>(
        x, W_lift, b_lift, h, N_NODES);

    const int MPL_GRID    = (N_NODES + MT - 1) / MT;   // 1250
    const int GATHER_GRID = (N_NODES + 7) / 8;          // 12500

    const float* bs[3] = { b1, b2, b3 };
    float* bufs[4] = { h, h2, h, h2 };

    for (int l = 0; l < 3; ++l) {
        float* hin  = bufs[l];
        float* hout = bufs[l + 1];
        gather_kernel<<<GATHER_GRID, 256>>>(hin, red);
        mpl_gemm_mma<<<MPL_GRID, THR, SA_BYTES>>>(
            hin, red, Bf + (size_t)l * NKF * KF_STRIDE, bs[l], hout, N_NODES);
    }

    // 3) output head
    out_kernel<<<(N_NODES + 255) / 256, 256>>>(h2, W_out, b_out, y, N_NODES);

    (void)in_sizes; (void)n_in; (void)out_size;
}

// round 14
// speedup vs baseline: 1.0932x; 1.0433x over previous
#include <cuda_runtime.h>
#include <cuda_bf16.h>
#include <math.h>
#include <stdint.h>

#define N_NODES 100000
#define N_EDGES 1600000
#define IN_F    16
#define HID     100
#define OUTF    3

// A' smem: hi section [0,208) + lo section [208,416), row stride 424 bf16
#define SEC    208
#define MT     80
#define THR    320         // 10 warps: 5 along M x 2 along N
#define A_STR  424
#define SA_BYTES (MT * A_STR * 2)   // 81408

// B image: [kf(39 = 3 sections x 13)][nu8(14 n8-blocks)][lane(32)] uint2
// warp_n=0 -> blocks 0..6 (cols 0..55), warp_n=1 -> blocks 7..13 (cols 56..111)
#define NKF    39
#define NU8    14
#define KF_STRIDE (NU8 * 32)        // uint2 elements per kf = 448

#define SCAN_B 1024
#define NBLK   ((N_NODES + SCAN_B - 1) / SCAN_B)   // 98

// ---------------------------------------------------------------------------
// Scratch (device globals; allocation APIs are forbidden)
// ---------------------------------------------------------------------------
__device__ __align__(16) float g_h  [N_NODES * HID];
__device__ __align__(16) float g_h2 [N_NODES * HID];
__device__ __align__(16) float g_red[N_NODES * HID];
__device__ __align__(16) uint2 g_Bfrag[3 * NKF * KF_STRIDE];
// CSR scratch
__device__ int   g_cnt   [N_NODES];
__device__ int   g_rowptr[N_NODES + 1];
__device__ int   g_cur   [N_NODES];
__device__ int   g_bsum  [NBLK];
__device__ int   g_bsumex[NBLK];
__device__ __align__(16) uint2 g_edge[N_EDGES];   // {src, w bits} sorted by dst

__device__ __forceinline__ uint32_t smem_u32(const void* p) {
    uint32_t a;
    asm("{ .reg .u64 t; cvta.to.shared.u64 t, %1; cvt.u32.u64 %0, t; }" : "=r"(a) : "l"(p));
    return a;
}
__device__ __forceinline__ uint32_t bf2_u32(__nv_bfloat162 v) {
    return *reinterpret_cast<uint32_t*>(&v);
}

#define LDSM4(r, addr)                                                           \
    asm volatile("ldmatrix.sync.aligned.m8n8.x4.shared.b16 {%0,%1,%2,%3}, [%4];" \
                 : "=r"((r)[0]), "=r"((r)[1]), "=r"((r)[2]), "=r"((r)[3])        \
                 : "r"(addr))

#define MMA16816(acc, a, bx, by)                                                 \
    asm volatile("mma.sync.aligned.m16n8k16.row.col.f32.bf16.bf16.f32 "          \
                 "{%0,%1,%2,%3}, {%4,%5,%6,%7}, {%8,%9}, {%0,%1,%2,%3};"         \
                 : "+f"((acc)[0]), "+f"((acc)[1]), "+f"((acc)[2]), "+f"((acc)[3])\
                 : "r"((a)[0]), "r"((a)[1]), "r"((a)[2]), "r"((a)[3]),           \
                   "r"(bx), "r"(by))

// ---------------------------------------------------------------------------
// CSR build
// ---------------------------------------------------------------------------
__global__ __launch_bounds__(256)
void hist_kernel(const int* __restrict__ dst) {
    int e = blockIdx.x * 256 + threadIdx.x;
    if (e < N_EDGES) atomicAdd(&g_cnt[dst[e]], 1);
}

__global__ __launch_bounds__(SCAN_B)
void block_sum_kernel() {
    __shared__ int s[SCAN_B];
    int i = blockIdx.x * SCAN_B + threadIdx.x;
    s[threadIdx.x] = (i < N_NODES) ? g_cnt[i] : 0;
    __syncthreads();
    for (int st = SCAN_B / 2; st > 0; st >>= 1) {
        if (threadIdx.x < st) s[threadIdx.x] += s[threadIdx.x + st];
        __syncthreads();
    }
    if (threadIdx.x == 0) g_bsum[blockIdx.x] = s[0];
}

__global__ __launch_bounds__(128)
void scan_bsum_kernel() {
    __shared__ int s[128];
    int t = threadIdx.x;
    int c = (t < NBLK) ? g_bsum[t] : 0;
    s[t] = c;
    __syncthreads();
    for (int st = 1; st < 128; st <<= 1) {
        int v = (t >= st) ? s[t - st] : 0;
        __syncthreads();
        s[t] += v;
        __syncthreads();
    }
    if (t < NBLK) g_bsumex[t] = s[t] - c;   // exclusive
}

__global__ __launch_bounds__(SCAN_B)
void rowptr_kernel() {
    __shared__ int s[SCAN_B];
    int i = blockIdx.x * SCAN_B + threadIdx.x;
    int c = (i < N_NODES) ? g_cnt[i] : 0;
    s[threadIdx.x] = c;
    __syncthreads();
    for (int st = 1; st < SCAN_B; st <<= 1) {
        int v = (threadIdx.x >= st) ? s[threadIdx.x - st] : 0;
        __syncthreads();
        s[threadIdx.x] += v;
        __syncthreads();
    }
    if (i < N_NODES) {
        int excl = g_bsumex[blockIdx.x] + s[threadIdx.x] - c;
        g_rowptr[i] = excl;
        g_cur[i]    = excl;
        if (i == N_NODES - 1) g_rowptr[N_NODES] = excl + c;
    }
}

__global__ __launch_bounds__(256)
void fill_kernel(const int* __restrict__ src, const int* __restrict__ dst,
                 const float* __restrict__ ef) {
    int e = blockIdx.x * 256 + threadIdx.x;
    if (e >= N_EDGES) return;
    int p = atomicAdd(&g_cur[dst[e]], 1);
    g_edge[p] = make_uint2((unsigned)src[e], __float_as_uint(ef[e]));
}

// ---------------------------------------------------------------------------
// Gather-reduce (CSR segment sum): red[n] = sum_e w_e * h[src_e]
// ---------------------------------------------------------------------------
__global__ __launch_bounds__(256)
void gather_kernel(const float* __restrict__ h, float* __restrict__ red) {
    const int wid  = threadIdx.x >> 5;
    const int lane = threadIdx.x & 31;
    const int n    = blockIdx.x * 8 + wid;
    if (n >= N_NODES) return;

    const int e0 = g_rowptr[n];
    const int e1 = g_rowptr[n + 1];
    float4 acc = make_float4(0.f, 0.f, 0.f, 0.f);

    int e = e0;
    for (; e + 2 <= e1; e += 2) {
        uint2 p0 = g_edge[e];
        uint2 p1 = g_edge[e + 1];
        float w0 = __uint_as_float(p0.y);
        float w1 = __uint_as_float(p1.y);
        if (lane < 25) {
            float4 v0 = *reinterpret_cast<const float4*>(h + (size_t)p0.x * HID + lane * 4);
            float4 v1 = *reinterpret_cast<const float4*>(h + (size_t)p1.x * HID + lane * 4);
            acc.x += w0 * v0.x + w1 * v1.x;
            acc.y += w0 * v0.y + w1 * v1.y;
            acc.z += w0 * v0.z + w1 * v1.z;
            acc.w += w0 * v0.w + w1 * v1.w;
        }
    }
    if (e < e1) {
        uint2 p0 = g_edge[e];
        float w0 = __uint_as_float(p0.y);
        if (lane < 25) {
            float4 v0 = *reinterpret_cast<const float4*>(h + (size_t)p0.x * HID + lane * 4);
            acc.x += w0 * v0.x; acc.y += w0 * v0.y;
            acc.z += w0 * v0.z; acc.w += w0 * v0.w;
        }
    }
    if (lane < 25)
        *reinterpret_cast<float4*>(red + (size_t)n * HID + lane * 4) = acc;
}

// ---------------------------------------------------------------------------
// Prep: pack B' (= W^T with hi/hi/lo sections) into per-n8 MMA B fragments.
// Layout: [l][kf(39)][nu8(14)][lane(32)] uint2 = {b0, b1} for block nu8.
// ---------------------------------------------------------------------------
__device__ __forceinline__ __nv_bfloat16 wconv(const float* W, int sec, int kk, int col) {
    float w = (kk < 2 * HID && col < HID) ? W[kk * HID + col] : 0.0f;
    __nv_bfloat16 hi = __float2bfloat16(w);
    return (sec == 2) ? __float2bfloat16(w - __bfloat162float(hi)) : hi;
}

__global__ __launch_bounds__(256)
void prep_B_kernel(const float* __restrict__ W1, const float* __restrict__ W2,
                   const float* __restrict__ W3)
{
    int i = blockIdx.x * 256 + threadIdx.x;
    if (i >= 3 * NKF * KF_STRIDE) return;
    int l    = i / (NKF * KF_STRIDE);
    int r    = i - l * (NKF * KF_STRIDE);
    int kf   = r / KF_STRIDE;
    int r2   = r - kf * KF_STRIDE;
    int nu8  = r2 >> 5;
    int lane = r2 & 31;

    int sec = kf / 13;
    int kk0 = (kf - sec * 13) * 16 + (lane & 3) * 2;
    int n   = nu8 * 8 + (lane >> 2);

    const float* W = (l == 0) ? W1 : (l == 1) ? W2 : W3;

    uint2 o;
    o.x = bf2_u32(__nv_bfloat162(wconv(W, sec, kk0,     n), wconv(W, sec, kk0 + 1, n)));
    o.y = bf2_u32(__nv_bfloat162(wconv(W, sec, kk0 + 8, n), wconv(W, sec, kk0 + 9, n)));
    g_Bfrag[i] = o;
}

// ---------------------------------------------------------------------------
// Mainloop phases: 7 n8 blocks per warp (balanced across warps/SMSPs).
// B via LDG.64 with distance-2 register prefetch (prefetch AFTER the last
// consumer of bb[cur][u] — the al MMA loop), A via ldmatrix distance-1.
// ---------------------------------------------------------------------------
__device__ __forceinline__ void phase_hi(float (*acc)[4], uint32_t aHi, uint32_t aLo,
                                         const uint2* __restrict__ bp)
{
    uint32_t ah[2][4], al[2][4];
    uint2 bb[2][7];
    LDSM4(ah[0], aHi);
    LDSM4(al[0], aLo);
#pragma unroll
    for (int u = 0; u < 7; ++u) {
        bb[0][u] = bp[u * 32];
        bb[1][u] = bp[KF_STRIDE + u * 32];
    }
#pragma unroll
    for (int k = 0; k < 13; ++k) {
        const int cur = k & 1, nxt = cur ^ 1;
        if (k + 1 < 13) {
            LDSM4(ah[nxt], aHi + (uint32_t)((k + 1) * 32));
            LDSM4(al[nxt], aLo + (uint32_t)((k + 1) * 32));
        }
#pragma unroll
        for (int u = 0; u < 7; ++u) {
            const uint2 bv = bb[cur][u];
            MMA16816(acc[u], ah[cur], bv.x, bv.y);
        }
#pragma unroll
        for (int u = 0; u < 7; ++u) {
            const uint2 bv = bb[cur][u];
            MMA16816(acc[u], al[cur], bv.x, bv.y);
            if (k + 2 < 13) bb[cur][u] = bp[(k + 2) * KF_STRIDE + u * 32];
        }
    }
}

__device__ __forceinline__ void phase_lo(float (*acc)[4], uint32_t aHi,
                                         const uint2* __restrict__ bp)
{
    uint32_t ah[2][4];
    uint2 bb[2][7];
    LDSM4(ah[0], aHi);
#pragma unroll
    for (int u = 0; u < 7; ++u) {
        bb[0][u] = bp[u * 32];
        bb[1][u] = bp[KF_STRIDE + u * 32];
    }
#pragma unroll
    for (int k = 0; k < 13; ++k) {
        const int cur = k & 1, nxt = cur ^ 1;
        if (k + 1 < 13) LDSM4(ah[nxt], aHi + (uint32_t)((k + 1) * 32));
#pragma unroll
        for (int u = 0; u < 7; ++u) {
            const uint2 bv = bb[cur][u];
            MMA16816(acc[u], ah[cur], bv.x, bv.y);
            if (k + 2 < 13) bb[cur][u] = bp[(k + 2) * KF_STRIDE + u * 32];
        }
    }
}

// ---------------------------------------------------------------------------
// MPL GEMM: out[n,0:100] = relu( concat(h[n], red[n]) @ W + b )
// N = 112 as 14 n8 blocks, 7 per warp -> every warp issues 273 MMAs.
// ---------------------------------------------------------------------------
__global__ __launch_bounds__(THR, 2)
void mpl_gemm_mma(const float* __restrict__ h,
                  const float* __restrict__ red,
                  const uint2* __restrict__ Bf,   // layer base in g_Bfrag
                  const float* __restrict__ b,
                  float* __restrict__ out,
                  int n_nodes)
{
    extern __shared__ __align__(16) uint8_t smem[];
    __nv_bfloat16* sA = reinterpret_cast<__nv_bfloat16*>(smem);
    const uint32_t sbase = smem_u32(smem);

    const int tid    = threadIdx.x;
    const int wid    = tid >> 5;
    const int lane   = tid & 31;
    const int warp_m = wid >> 1;         // 0..4
    const int warp_n = wid & 1;          // 0..1
    const int node0  = blockIdx.x * MT;

    // ---- fill A' once: hi at [0,208), lo at [208,416) ----
    for (int i = tid; i < MT * 52; i += THR) {
        int row = i / 52;
        int kk  = (i - row * 52) * 4;
        int n   = node0 + row;
        float4 v = make_float4(0.f, 0.f, 0.f, 0.f);
        if (n < n_nodes) {
            if (kk < HID)          v = *reinterpret_cast<const float4*>(h + (size_t)n * HID + kk);
            else if (kk < 2 * HID) v = *reinterpret_cast<const float4*>(red + (size_t)n * HID + kk - HID);
        }
        __nv_bfloat162 h0 = __floats2bfloat162_rn(v.x, v.y);
        __nv_bfloat162 h1 = __floats2bfloat162_rn(v.z, v.w);
        __nv_bfloat162 l0 = __floats2bfloat162_rn(v.x - __bfloat162float(h0.x),
                                                  v.y - __bfloat162float(h0.y));
        __nv_bfloat162 l1 = __floats2bfloat162_rn(v.z - __bfloat162float(h1.x),
                                                  v.w - __bfloat162float(h1.y));
        __nv_bfloat16* rp = sA + row * A_STR;
        *reinterpret_cast<uint2*>(rp + kk)       = make_uint2(bf2_u32(h0), bf2_u32(h1));
        *reinterpret_cast<uint2*>(rp + SEC + kk) = make_uint2(bf2_u32(l0), bf2_u32(l1));
    }
    __syncthreads();

    float acc[7][4];
#pragma unroll
    for (int f = 0; f < 7; ++f)
#pragma unroll
        for (int j = 0; j < 4; ++j) acc[f][j] = 0.0f;

    const int lrow  = lane & 15;
    const int lkoff = (lane >> 4) << 3;
    const uint32_t aHi = sbase + (uint32_t)(((warp_m * 16 + lrow) * A_STR + lkoff) * 2);
    const uint32_t aLo = aHi + SEC * 2;
    // warp's B pointer: n8 blocks [warp_n*7 .. warp_n*7+7)
    const uint2* bp  = Bf + warp_n * 7 * 32 + lane;          // kf 0 (hi)
    const uint2* bp2 = bp + (size_t)26 * KF_STRIDE;          // kf 26 (lo)

    phase_hi(acc, aHi, aLo, bp);
    phase_lo(acc, aHi, bp2);

    // ---- epilogue: bias + relu + float2 stores ----
    const int gr = lane >> 2;
    const int tc = lane & 3;
    const int r0 = node0 + warp_m * 16 + gr;
    const int r1 = r0 + 8;
#pragma unroll
    for (int f = 0; f < 7; ++f) {
        int col = warp_n * 56 + f * 8 + tc * 2;
        if (col < HID) {
            float b0 = b[col], b1 = b[col + 1];
            if (r0 < n_nodes) {
                float2 v;
                v.x = fmaxf(acc[f][0] + b0, 0.f);
                v.y = fmaxf(acc[f][1] + b1, 0.f);
                *reinterpret_cast<float2*>(out + (size_t)r0 * HID + col) = v;
            }
            if (r1 < n_nodes) {
                float2 v;
                v.x = fmaxf(acc[f][2] + b0, 0.f);
                v.y = fmaxf(acc[f][3] + b1, 0.f);
                *reinterpret_cast<float2*>(out + (size_t)r1 * HID + col) = v;
            }
        }
    }
}

// ---------------------------------------------------------------------------
// Lift GEMM (FFMA; tiny K=16): h = tanh(x @ W_lift + b_lift)
// ---------------------------------------------------------------------------
template <int KDIM>
__global__ __launch_bounds__(512, 1)
void lift_gemm_kernel(const float* __restrict__ in1,
                      const float* __restrict__ W,
                      const float* __restrict__ b,
                      float* __restrict__ out,
                      int n_nodes)
{
    extern __shared__ float sm[];
    constexpr int SSTR = KDIM + 4;
    float* sW  = sm;
    float* sIn = sm + KDIM * 128;

    const int tid   = threadIdx.x;
    const int node0 = blockIdx.x * 128;

    for (int i = tid; i < KDIM * 128; i += 512) {
        int k = i >> 7, c = i & 127;
        sW[i] = (c < HID) ? W[k * HID + c] : 0.0f;
    }
    for (int i = tid; i < 128 * KDIM; i += 512) {
        int nl = i / KDIM, k = i - nl * KDIM;
        int n  = node0 + nl;
        sIn[nl * SSTR + k] = (n < n_nodes) ? in1[n * KDIM + k] : 0.0f;
    }
    __syncthreads();

    const int lane = tid & 31;
    const int wp   = tid >> 5;
    const float* abase = sIn + wp * 8 * SSTR;
    const float* wbase = sW + lane * 4;

    float4 acc[8];
#pragma unroll
    for (int j = 0; j < 8; ++j) acc[j] = make_float4(0.f, 0.f, 0.f, 0.f);

#pragma unroll
    for (int k0 = 0; k0 < KDIM; k0 += 4) {
        const float4 w0 = *reinterpret_cast<const float4*>(wbase + (k0 + 0) * 128);
        const float4 w1 = *reinterpret_cast<const float4*>(wbase + (k0 + 1) * 128);
        const float4 w2 = *reinterpret_cast<const float4*>(wbase + (k0 + 2) * 128);
        const float4 w3 = *reinterpret_cast<const float4*>(wbase + (k0 + 3) * 128);
#pragma unroll
        for (int j = 0; j < 8; ++j) {
            const float4 a = *reinterpret_cast<const float4*>(abase + j * SSTR + k0);
            acc[j].x += a.x * w0.x; acc[j].y += a.x * w0.y; acc[j].z += a.x * w0.z; acc[j].w += a.x * w0.w;
            acc[j].x += a.y * w1.x; acc[j].y += a.y * w1.y; acc[j].z += a.y * w1.z; acc[j].w += a.y * w1.w;
            acc[j].x += a.z * w2.x; acc[j].y += a.z * w2.y; acc[j].z += a.z * w2.z; acc[j].w += a.z * w2.w;
            acc[j].x += a.w * w3.x; acc[j].y += a.w * w3.y; acc[j].z += a.w * w3.z; acc[j].w += a.w * w3.w;
        }
    }

    if (lane < 25) {
        const float4 bias = *reinterpret_cast<const float4*>(b + lane * 4);
#pragma unroll
        for (int j = 0; j < 8; ++j) {
            int n = node0 + wp * 8 + j;
            if (n < n_nodes) {
                float4 r;
                r.x = tanhf(acc[j].x + bias.x); r.y = tanhf(acc[j].y + bias.y);
                r.z = tanhf(acc[j].z + bias.z); r.w = tanhf(acc[j].w + bias.w);
                *reinterpret_cast<float4*>(out + (size_t)n * HID + lane * 4) = r;
            }
        }
    }
}

// ---------------------------------------------------------------------------
// Output head: y[n] = sigmoid(h[n,0:100] @ W_out[100x3] + b_out)
// ---------------------------------------------------------------------------
__global__ __launch_bounds__(256)
void out_kernel(const float* __restrict__ h,
                const float* __restrict__ Wo,
                const float* __restrict__ bo,
                float* __restrict__ y,
                int n_nodes)
{
    __shared__ float sW[HID * OUTF];
    int tid = threadIdx.x;
    for (int i = tid; i < HID * OUTF; i += 256) sW[i] = Wo[i];
    __syncthreads();

    int node = blockIdx.x * 256 + tid;
    if (node >= n_nodes) return;

    float a0 = bo[0], a1 = bo[1], a2 = bo[2];
    const float4* hv = reinterpret_cast<const float4*>(h + (size_t)node * HID);
#pragma unroll
    for (int kb = 0; kb < 25; ++kb) {
        float4 v = hv[kb];
        int k = kb * 4;
        a0 += v.x * sW[(k+0)*3+0]; a1 += v.x * sW[(k+0)*3+1]; a2 += v.x * sW[(k+0)*3+2];
        a0 += v.y * sW[(k+1)*3+0]; a1 += v.y * sW[(k+1)*3+1]; a2 += v.y * sW[(k+1)*3+2];
        a0 += v.z * sW[(k+2)*3+0]; a1 += v.z * sW[(k+2)*3+1]; a2 += v.z * sW[(k+2)*3+2];
        a0 += v.w * sW[(k+3)*3+0]; a1 += v.w * sW[(k+3)*3+1]; a2 += v.w * sW[(k+3)*3+2];
    }
    y[(size_t)node * 3 + 0] = 1.0f / (1.0f + expf(-a0));
    y[(size_t)node * 3 + 1] = 1.0f / (1.0f + expf(-a1));
    y[(size_t)node * 3 + 2] = 1.0f / (1.0f + expf(-a2));
}

// ---------------------------------------------------------------------------
extern "C" void kernel_launch(void* const* d_in, const int* in_sizes, int n_in,
                              void* d_out, int out_size)
{
    const float* x      = (const float*)d_in[0];
    const float* ef     = (const float*)d_in[1];
    const int*   src    = (const int*)  d_in[2];
    const int*   dst    = (const int*)  d_in[3];
    const float* W_lift = (const float*)d_in[4];
    const float* b_lift = (const float*)d_in[5];
    const float* W1     = (const float*)d_in[6];
    const float* b1     = (const float*)d_in[7];
    const float* W2     = (const float*)d_in[8];
    const float* b2     = (const float*)d_in[9];
    const float* W3     = (const float*)d_in[10];
    const float* b3     = (const float*)d_in[11];
    const float* W_out  = (const float*)d_in[12];
    const float* b_out  = (const float*)d_in[13];
    float* y = (float*)d_out;

    float *h, *h2, *red;
    uint2* Bf;
    int* cnt;
    cudaGetSymbolAddress((void**)&h,   g_h);
    cudaGetSymbolAddress((void**)&h2,  g_h2);
    cudaGetSymbolAddress((void**)&red, g_red);
    cudaGetSymbolAddress((void**)&Bf,  g_Bfrag);
    cudaGetSymbolAddress((void**)&cnt, g_cnt);

    const size_t SMEM_LIFT = (IN_F * 128 + 128 * (IN_F + 4)) * sizeof(float);

    cudaFuncSetAttribute((const void*)mpl_gemm_mma,
                         cudaFuncAttributeMaxDynamicSharedMemorySize, SA_BYTES);

    // 0) weight prep + CSR build (once per launch)
    prep_B_kernel<<<(3 * NKF * KF_STRIDE + 255) / 256, 256>>>(W1, W2, W3);
    cudaMemsetAsync(cnt, 0, N_NODES * sizeof(int));
    hist_kernel<<<(N_EDGES + 255) / 256, 256>>>(dst);
    block_sum_kernel<<<NBLK, SCAN_B>>>();
    scan_bsum_kernel<<<1, 128>>>();
    rowptr_kernel<<<NBLK, SCAN_B>>>();
    fill_kernel<<<(N_EDGES + 255) / 256, 256>>>(src, dst, ef);

    // 1) lift
    lift_gemm_kernel<IN_F><<<(N_NODES + 127) / 128, 512, SMEM_LIFT>>>(
        x, W_lift, b_lift, h, N_NODES);

    const int MPL_GRID    = (N_NODES + MT - 1) / MT;   // 1250
    const int GATHER_GRID = (N_NODES + 7) / 8;          // 12500

    const float* bs[3] = { b1, b2, b3 };
    float* bufs[4] = { h, h2, h, h2 };

    for (int l = 0; l < 3; ++l) {
        float* hin  = bufs[l];
        float* hout = bufs[l + 1];
        gather_kernel<<<GATHER_GRID, 256>>>(hin, red);
        mpl_gemm_mma<<<MPL_GRID, THR, SA_BYTES>>>(
            hin, red, Bf + (size_t)l * NKF * KF_STRIDE, bs[l], hout, N_NODES);
    }

    // 3) output head
    out_kernel<<<(N_NODES + 255) / 256, 256>>>(h2, W_out, b_out, y, N_NODES);

    (void)in_sizes; (void)n_in; (void)out_size;
}

// round 15
// speedup vs baseline: 1.1910x; 1.0895x over previous
#include <cuda_runtime.h>
#include <cuda_fp16.h>
#include <math.h>
#include <stdint.h>

#define N_NODES 100000
#define N_EDGES 1600000
#define IN_F    16
#define HID     100
#define OUTF    3

// A' smem: fp16 hi section [0,208) + fp16 lo section [208,416), stride 424
#define SEC    208
#define MT     80
#define THR    320         // 10 warps: 5 along M x 2 along N
#define A_STR  424
#define SA_BYTES (MT * A_STR * 2)   // 81408

// B image (single fp16 section): [kf(13)][nu8(14 n8-blocks)][lane(32)] uint2
// warp_n=0 -> blocks 0..6 (cols 0..55), warp_n=1 -> blocks 7..13 (cols 56..111)
#define NKF    13
#define NU8    14
#define KF_STRIDE (NU8 * 32)        // uint2 elements per kf = 448

#define SCAN_B 1024
#define NBLK   ((N_NODES + SCAN_B - 1) / SCAN_B)   // 98

// ---------------------------------------------------------------------------
// Scratch (device globals; allocation APIs are forbidden)
// ---------------------------------------------------------------------------
__device__ __align__(16) float g_h  [N_NODES * HID];
__device__ __align__(16) float g_h2 [N_NODES * HID];
__device__ __align__(16) float g_red[N_NODES * HID];
__device__ __align__(16) uint2 g_Bfrag[3 * NKF * KF_STRIDE];
// CSR scratch
__device__ int   g_cnt   [N_NODES];
__device__ int   g_rowptr[N_NODES + 1];
__device__ int   g_cur   [N_NODES];
__device__ int   g_bsum  [NBLK];
__device__ int   g_bsumex[NBLK];
__device__ __align__(16) uint2 g_edge[N_EDGES];   // {src, w bits} sorted by dst

__device__ __forceinline__ uint32_t smem_u32(const void* p) {
    uint32_t a;
    asm("{ .reg .u64 t; cvta.to.shared.u64 t, %1; cvt.u32.u64 %0, t; }" : "=r"(a) : "l"(p));
    return a;
}
__device__ __forceinline__ uint32_t h2_u32(__half2 v) {
    return *reinterpret_cast<uint32_t*>(&v);
}

#define LDSM4(r, addr)                                                           \
    asm volatile("ldmatrix.sync.aligned.m8n8.x4.shared.b16 {%0,%1,%2,%3}, [%4];" \
                 : "=r"((r)[0]), "=r"((r)[1]), "=r"((r)[2]), "=r"((r)[3])        \
                 : "r"(addr))

#define MMA16816(acc, a, bx, by)                                                 \
    asm volatile("mma.sync.aligned.m16n8k16.row.col.f32.f16.f16.f32 "            \
                 "{%0,%1,%2,%3}, {%4,%5,%6,%7}, {%8,%9}, {%0,%1,%2,%3};"         \
                 : "+f"((acc)[0]), "+f"((acc)[1]), "+f"((acc)[2]), "+f"((acc)[3])\
                 : "r"((a)[0]), "r"((a)[1]), "r"((a)[2]), "r"((a)[3]),           \
                   "r"(bx), "r"(by))

// ---------------------------------------------------------------------------
// CSR build
// ---------------------------------------------------------------------------
__global__ __launch_bounds__(256)
void hist_kernel(const int* __restrict__ dst) {
    int e = blockIdx.x * 256 + threadIdx.x;
    if (e < N_EDGES) atomicAdd(&g_cnt[dst[e]], 1);
}

__global__ __launch_bounds__(SCAN_B)
void block_sum_kernel() {
    __shared__ int s[SCAN_B];
    int i = blockIdx.x * SCAN_B + threadIdx.x;
    s[threadIdx.x] = (i < N_NODES) ? g_cnt[i] : 0;
    __syncthreads();
    for (int st = SCAN_B / 2; st > 0; st >>= 1) {
        if (threadIdx.x < st) s[threadIdx.x] += s[threadIdx.x + st];
        __syncthreads();
    }
    if (threadIdx.x == 0) g_bsum[blockIdx.x] = s[0];
}

__global__ __launch_bounds__(128)
void scan_bsum_kernel() {
    __shared__ int s[128];
    int t = threadIdx.x;
    int c = (t < NBLK) ? g_bsum[t] : 0;
    s[t] = c;
    __syncthreads();
    for (int st = 1; st < 128; st <<= 1) {
        int v = (t >= st) ? s[t - st] : 0;
        __syncthreads();
        s[t] += v;
        __syncthreads();
    }
    if (t < NBLK) g_bsumex[t] = s[t] - c;   // exclusive
}

__global__ __launch_bounds__(SCAN_B)
void rowptr_kernel() {
    __shared__ int s[SCAN_B];
    int i = blockIdx.x * SCAN_B + threadIdx.x;
    int c = (i < N_NODES) ? g_cnt[i] : 0;
    s[threadIdx.x] = c;
    __syncthreads();
    for (int st = 1; st < SCAN_B; st <<= 1) {
        int v = (threadIdx.x >= st) ? s[threadIdx.x - st] : 0;
        __syncthreads();
        s[threadIdx.x] += v;
        __syncthreads();
    }
    if (i < N_NODES) {
        int excl = g_bsumex[blockIdx.x] + s[threadIdx.x] - c;
        g_rowptr[i] = excl;
        g_cur[i]    = excl;
        if (i == N_NODES - 1) g_rowptr[N_NODES] = excl + c;
    }
}

__global__ __launch_bounds__(256)
void fill_kernel(const int* __restrict__ src, const int* __restrict__ dst,
                 const float* __restrict__ ef) {
    int e = blockIdx.x * 256 + threadIdx.x;
    if (e >= N_EDGES) return;
    int p = atomicAdd(&g_cur[dst[e]], 1);
    g_edge[p] = make_uint2((unsigned)src[e], __float_as_uint(ef[e]));
}

// ---------------------------------------------------------------------------
// Gather-reduce (CSR segment sum): red[n] = sum_e w_e * h[src_e]
// ---------------------------------------------------------------------------
__global__ __launch_bounds__(256)
void gather_kernel(const float* __restrict__ h, float* __restrict__ red) {
    const int wid  = threadIdx.x >> 5;
    const int lane = threadIdx.x & 31;
    const int n    = blockIdx.x * 8 + wid;
    if (n >= N_NODES) return;

    const int e0 = g_rowptr[n];
    const int e1 = g_rowptr[n + 1];
    float4 acc = make_float4(0.f, 0.f, 0.f, 0.f);

    int e = e0;
    for (; e + 2 <= e1; e += 2) {
        uint2 p0 = g_edge[e];
        uint2 p1 = g_edge[e + 1];
        float w0 = __uint_as_float(p0.y);
        float w1 = __uint_as_float(p1.y);
        if (lane < 25) {
            float4 v0 = *reinterpret_cast<const float4*>(h + (size_t)p0.x * HID + lane * 4);
            float4 v1 = *reinterpret_cast<const float4*>(h + (size_t)p1.x * HID + lane * 4);
            acc.x += w0 * v0.x + w1 * v1.x;
            acc.y += w0 * v0.y + w1 * v1.y;
            acc.z += w0 * v0.z + w1 * v1.z;
            acc.w += w0 * v0.w + w1 * v1.w;
        }
    }
    if (e < e1) {
        uint2 p0 = g_edge[e];
        float w0 = __uint_as_float(p0.y);
        if (lane < 25) {
            float4 v0 = *reinterpret_cast<const float4*>(h + (size_t)p0.x * HID + lane * 4);
            acc.x += w0 * v0.x; acc.y += w0 * v0.y;
            acc.z += w0 * v0.z; acc.w += w0 * v0.w;
        }
    }
    if (lane < 25)
        *reinterpret_cast<float4*>(red + (size_t)n * HID + lane * 4) = acc;
}

// ---------------------------------------------------------------------------
// Prep: pack B = fp16(W^T) into per-n8 MMA B fragments.
// Layout: [l][kf(13)][nu8(14)][lane(32)] uint2 = {b0, b1} for block nu8.
// ---------------------------------------------------------------------------
__device__ __forceinline__ __half wconvh(const float* W, int kk, int col) {
    float w = (kk < 2 * HID && col < HID) ? W[kk * HID + col] : 0.0f;
    return __float2half_rn(w);
}

__global__ __launch_bounds__(256)
void prep_B_kernel(const float* __restrict__ W1, const float* __restrict__ W2,
                   const float* __restrict__ W3)
{
    int i = blockIdx.x * 256 + threadIdx.x;
    if (i >= 3 * NKF * KF_STRIDE) return;
    int l    = i / (NKF * KF_STRIDE);
    int r    = i - l * (NKF * KF_STRIDE);
    int kf   = r / KF_STRIDE;
    int r2   = r - kf * KF_STRIDE;
    int nu8  = r2 >> 5;
    int lane = r2 & 31;

    int kk0 = kf * 16 + (lane & 3) * 2;
    int n   = nu8 * 8 + (lane >> 2);

    const float* W = (l == 0) ? W1 : (l == 1) ? W2 : W3;

    uint2 o;
    o.x = h2_u32(__half2(wconvh(W, kk0,     n), wconvh(W, kk0 + 1, n)));
    o.y = h2_u32(__half2(wconvh(W, kk0 + 8, n), wconvh(W, kk0 + 9, n)));
    g_Bfrag[i] = o;
}

// ---------------------------------------------------------------------------
// MPL GEMM: out[n,0:100] = relu( concat(h[n], red[n]) @ W + b )
// fp16 2-term: D = A_hi*B + A_lo*B. B (single fp16) loaded once per kf and
// consumed by both A terms -> 182 MMAs/warp (balanced across all SMSPs).
// B via LDG.64 with distance-2 register prefetch (prefetch AFTER the al MMA,
// the last consumer of bb[cur][u]); A via ldmatrix distance-1.
// ---------------------------------------------------------------------------
__global__ __launch_bounds__(THR, 2)
void mpl_gemm_mma(const float* __restrict__ h,
                  const float* __restrict__ red,
                  const uint2* __restrict__ Bf,   // layer base in g_Bfrag
                  const float* __restrict__ b,
                  float* __restrict__ out,
                  int n_nodes)
{
    extern __shared__ __align__(16) uint8_t smem[];
    __half* sA = reinterpret_cast<__half*>(smem);
    const uint32_t sbase = smem_u32(smem);

    const int tid    = threadIdx.x;
    const int wid    = tid >> 5;
    const int lane   = tid & 31;
    const int warp_m = wid >> 1;         // 0..4
    const int warp_n = wid & 1;          // 0..1
    const int node0  = blockIdx.x * MT;

    // ---- fill A' once: fp16 hi at [0,208), fp16 lo at [208,416) ----
    for (int i = tid; i < MT * 52; i += THR) {
        int row = i / 52;
        int kk  = (i - row * 52) * 4;
        int n   = node0 + row;
        float4 v = make_float4(0.f, 0.f, 0.f, 0.f);
        if (n < n_nodes) {
            if (kk < HID)          v = *reinterpret_cast<const float4*>(h + (size_t)n * HID + kk);
            else if (kk < 2 * HID) v = *reinterpret_cast<const float4*>(red + (size_t)n * HID + kk - HID);
        }
        __half2 h0 = __floats2half2_rn(v.x, v.y);
        __half2 h1 = __floats2half2_rn(v.z, v.w);
        __half2 l0 = __floats2half2_rn(v.x - __half2float(h0.x),
                                       v.y - __half2float(h0.y));
        __half2 l1 = __floats2half2_rn(v.z - __half2float(h1.x),
                                       v.w - __half2float(h1.y));
        __half* rp = sA + row * A_STR;
        *reinterpret_cast<uint2*>(rp + kk)       = make_uint2(h2_u32(h0), h2_u32(h1));
        *reinterpret_cast<uint2*>(rp + SEC + kk) = make_uint2(h2_u32(l0), h2_u32(l1));
    }
    __syncthreads();

    float acc[7][4];
#pragma unroll
    for (int f = 0; f < 7; ++f)
#pragma unroll
        for (int j = 0; j < 4; ++j) acc[f][j] = 0.0f;

    const int lrow  = lane & 15;
    const int lkoff = (lane >> 4) << 3;
    const uint32_t aHi = sbase + (uint32_t)(((warp_m * 16 + lrow) * A_STR + lkoff) * 2);
    const uint32_t aLo = aHi + SEC * 2;
    // warp's B pointer: n8 blocks [warp_n*7 .. warp_n*7+7)
    const uint2* bp = Bf + warp_n * 7 * 32 + lane;

    uint32_t ah[2][4], al[2][4];
    uint2 bb[2][7];
    LDSM4(ah[0], aHi);
    LDSM4(al[0], aLo);
#pragma unroll
    for (int u = 0; u < 7; ++u) {
        bb[0][u] = bp[u * 32];
        bb[1][u] = bp[KF_STRIDE + u * 32];
    }
#pragma unroll
    for (int k = 0; k < NKF; ++k) {
        const int cur = k & 1, nxt = cur ^ 1;
        if (k + 1 < NKF) {
            LDSM4(ah[nxt], aHi + (uint32_t)((k + 1) * 32));
            LDSM4(al[nxt], aLo + (uint32_t)((k + 1) * 32));
        }
#pragma unroll
        for (int u = 0; u < 7; ++u) {
            const uint2 bv = bb[cur][u];
            MMA16816(acc[u], ah[cur], bv.x, bv.y);
        }
#pragma unroll
        for (int u = 0; u < 7; ++u) {
            const uint2 bv = bb[cur][u];
            MMA16816(acc[u], al[cur], bv.x, bv.y);
            if (k + 2 < NKF) bb[cur][u] = bp[(k + 2) * KF_STRIDE + u * 32];
        }
    }

    // ---- epilogue: bias + relu + float2 stores ----
    const int gr = lane >> 2;
    const int tc = lane & 3;
    const int r0 = node0 + warp_m * 16 + gr;
    const int r1 = r0 + 8;
#pragma unroll
    for (int f = 0; f < 7; ++f) {
        int col = warp_n * 56 + f * 8 + tc * 2;
        if (col < HID) {
            float b0 = b[col], b1 = b[col + 1];
            if (r0 < n_nodes) {
                float2 v;
                v.x = fmaxf(acc[f][0] + b0, 0.f);
                v.y = fmaxf(acc[f][1] + b1, 0.f);
                *reinterpret_cast<float2*>(out + (size_t)r0 * HID + col) = v;
            }
            if (r1 < n_nodes) {
                float2 v;
                v.x = fmaxf(acc[f][2] + b0, 0.f);
                v.y = fmaxf(acc[f][3] + b1, 0.f);
                *reinterpret_cast<float2*>(out + (size_t)r1 * HID + col) = v;
            }
        }
    }
}

// ---------------------------------------------------------------------------
// Lift GEMM (FFMA; tiny K=16): h = tanh(x @ W_lift + b_lift)
// ---------------------------------------------------------------------------
template <int KDIM>
__global__ __launch_bounds__(512, 1)
void lift_gemm_kernel(const float* __restrict__ in1,
                      const float* __restrict__ W,
                      const float* __restrict__ b,
                      float* __restrict__ out,
                      int n_nodes)
{
    extern __shared__ float sm[];
    constexpr int SSTR = KDIM + 4;
    float* sW  = sm;
    float* sIn = sm + KDIM * 128;

    const int tid   = threadIdx.x;
    const int node0 = blockIdx.x * 128;

    for (int i = tid; i < KDIM * 128; i += 512) {
        int k = i >> 7, c = i & 127;
        sW[i] = (c < HID) ? W[k * HID + c] : 0.0f;
    }
    for (int i = tid; i < 128 * KDIM; i += 512) {
        int nl = i / KDIM, k = i - nl * KDIM;
        int n  = node0 + nl;
        sIn[nl * SSTR + k] = (n < n_nodes) ? in1[n * KDIM + k] : 0.0f;
    }
    __syncthreads();

    const int lane = tid & 31;
    const int wp   = tid >> 5;
    const float* abase = sIn + wp * 8 * SSTR;
    const float* wbase = sW + lane * 4;

    float4 acc[8];
#pragma unroll
    for (int j = 0; j < 8; ++j) acc[j] = make_float4(0.f, 0.f, 0.f, 0.f);

#pragma unroll
    for (int k0 = 0; k0 < KDIM; k0 += 4) {
        const float4 w0 = *reinterpret_cast<const float4*>(wbase + (k0 + 0) * 128);
        const float4 w1 = *reinterpret_cast<const float4*>(wbase + (k0 + 1) * 128);
        const float4 w2 = *reinterpret_cast<const float4*>(wbase + (k0 + 2) * 128);
        const float4 w3 = *reinterpret_cast<const float4*>(wbase + (k0 + 3) * 128);
#pragma unroll
        for (int j = 0; j < 8; ++j) {
            const float4 a = *reinterpret_cast<const float4*>(abase + j * SSTR + k0);
            acc[j].x += a.x * w0.x; acc[j].y += a.x * w0.y; acc[j].z += a.x * w0.z; acc[j].w += a.x * w0.w;
            acc[j].x += a.y * w1.x; acc[j].y += a.y * w1.y; acc[j].z += a.y * w1.z; acc[j].w += a.y * w1.w;
            acc[j].x += a.z * w2.x; acc[j].y += a.z * w2.y; acc[j].z += a.z * w2.z; acc[j].w += a.z * w2.w;
            acc[j].x += a.w * w3.x; acc[j].y += a.w * w3.y; acc[j].z += a.w * w3.z; acc[j].w += a.w * w3.w;
        }
    }

    if (lane < 25) {
        const float4 bias = *reinterpret_cast<const float4*>(b + lane * 4);
#pragma unroll
        for (int j = 0; j < 8; ++j) {
            int n = node0 + wp * 8 + j;
            if (n < n_nodes) {
                float4 r;
                r.x = tanhf(acc[j].x + bias.x); r.y = tanhf(acc[j].y + bias.y);
                r.z = tanhf(acc[j].z + bias.z); r.w = tanhf(acc[j].w + bias.w);
                *reinterpret_cast<float4*>(out + (size_t)n * HID + lane * 4) = r;
            }
        }
    }
}

// ---------------------------------------------------------------------------
// Output head: y[n] = sigmoid(h[n,0:100] @ W_out[100x3] + b_out)
// ---------------------------------------------------------------------------
__global__ __launch_bounds__(256)
void out_kernel(const float* __restrict__ h,
                const float* __restrict__ Wo,
                const float* __restrict__ bo,
                float* __restrict__ y,
                int n_nodes)
{
    __shared__ float sW[HID * OUTF];
    int tid = threadIdx.x;
    for (int i = tid; i < HID * OUTF; i += 256) sW[i] = Wo[i];
    __syncthreads();

    int node = blockIdx.x * 256 + tid;
    if (node >= n_nodes) return;

    float a0 = bo[0], a1 = bo[1], a2 = bo[2];
    const float4* hv = reinterpret_cast<const float4*>(h + (size_t)node * HID);
#pragma unroll
    for (int kb = 0; kb < 25; ++kb) {
        float4 v = hv[kb];
        int k = kb * 4;
        a0 += v.x * sW[(k+0)*3+0]; a1 += v.x * sW[(k+0)*3+1]; a2 += v.x * sW[(k+0)*3+2];
        a0 += v.y * sW[(k+1)*3+0]; a1 += v.y * sW[(k+1)*3+1]; a2 += v.y * sW[(k+1)*3+2];
        a0 += v.z * sW[(k+2)*3+0]; a1 += v.z * sW[(k+2)*3+1]; a2 += v.z * sW[(k+2)*3+2];
        a0 += v.w * sW[(k+3)*3+0]; a1 += v.w * sW[(k+3)*3+1]; a2 += v.w * sW[(k+3)*3+2];
    }
    y[(size_t)node * 3 + 0] = 1.0f / (1.0f + expf(-a0));
    y[(size_t)node * 3 + 1] = 1.0f / (1.0f + expf(-a1));
    y[(size_t)node * 3 + 2] = 1.0f / (1.0f + expf(-a2));
}

// ---------------------------------------------------------------------------
extern "C" void kernel_launch(void* const* d_in, const int* in_sizes, int n_in,
                              void* d_out, int out_size)
{
    const float* x      = (const float*)d_in[0];
    const float* ef     = (const float*)d_in[1];
    const int*   src    = (const int*)  d_in[2];
    const int*   dst    = (const int*)  d_in[3];
    const float* W_lift = (const float*)d_in[4];
    const float* b_lift = (const float*)d_in[5];
    const float* W1     = (const float*)d_in[6];
    const float* b1     = (const float*)d_in[7];
    const float* W2     = (const float*)d_in[8];
    const float* b2     = (const float*)d_in[9];
    const float* W3     = (const float*)d_in[10];
    const float* b3     = (const float*)d_in[11];
    const float* W_out  = (const float*)d_in[12];
    const float* b_out  = (const float*)d_in[13];
    float* y = (float*)d_out;

    float *h, *h2, *red;
    uint2* Bf;
    int* cnt;
    cudaGetSymbolAddress((void**)&h,   g_h);
    cudaGetSymbolAddress((void**)&h2,  g_h2);
    cudaGetSymbolAddress((void**)&red, g_red);
    cudaGetSymbolAddress((void**)&Bf,  g_Bfrag);
    cudaGetSymbolAddress((void**)&cnt, g_cnt);

    const size_t SMEM_LIFT = (IN_F * 128 + 128 * (IN_F + 4)) * sizeof(float);

    cudaFuncSetAttribute((const void*)mpl_gemm_mma,
                         cudaFuncAttributeMaxDynamicSharedMemorySize, SA_BYTES);

    // 0) weight prep + CSR build (once per launch)
    prep_B_kernel<<<(3 * NKF * KF_STRIDE + 255) / 256, 256>>>(W1, W2, W3);
    cudaMemsetAsync(cnt, 0, N_NODES * sizeof(int));
    hist_kernel<<<(N_EDGES + 255) / 256, 256>>>(dst);
    block_sum_kernel<<<NBLK, SCAN_B>>>();
    scan_bsum_kernel<<<1, 128>>>();
    rowptr_kernel<<<NBLK, SCAN_B>>>();
    fill_kernel<<<(N_EDGES + 255) / 256, 256>>>(src, dst, ef);

    // 1) lift
    lift_gemm_kernel<IN_F><<<(N_NODES + 127) / 128, 512, SMEM_LIFT>>>(
        x, W_lift, b_lift, h, N_NODES);

    const int MPL_GRID    = (N_NODES + MT - 1) / MT;   // 1250
    const int GATHER_GRID = (N_NODES + 7) / 8;          // 12500

    const float* bs[3] = { b1, b2, b3 };
    float* bufs[4] = { h, h2, h, h2 };

    for (int l = 0; l < 3; ++l) {
        float* hin  = bufs[l];
        float* hout = bufs[l + 1];
        gather_kernel<<<GATHER_GRID, 256>>>(hin, red);
        mpl_gemm_mma<<<MPL_GRID, THR, SA_BYTES>>>(
            hin, red, Bf + (size_t)l * NKF * KF_STRIDE, bs[l], hout, N_NODES);
    }

    // 3) output head
    out_kernel<<<(N_NODES + 255) / 256, 256>>>(h2, W_out, b_out, y, N_NODES);

    (void)in_sizes; (void)n_in; (void)out_size;
}

// round 16
// speedup vs baseline: 1.2215x; 1.0256x over previous
#include <cuda_runtime.h>
#include <cuda_fp16.h>
#include <math.h>
#include <stdint.h>

#define N_NODES 100000
#define N_EDGES 1600000
#define IN_F    16
#define HID     100
#define OUTF    3

// A smem: single fp16 section [0,208), row stride 216 (432B -> ldmatrix
// conflict-free: successive rows step 27 16B-units = 3 bank-groups mod 8)
#define SEC    208
#define MT     80
#define THR    320         // 10 warps: 5 along M x 2 along N
#define A_STR  216
#define SA_BYTES (MT * A_STR * 2)   // 34560

// B image (single fp16 section): [kf(13)][nu8(14 n8-blocks)][lane(32)] uint2
// warp_n=0 -> blocks 0..6 (cols 0..55), warp_n=1 -> blocks 7..13 (cols 56..111)
#define NKF    13
#define NU8    14
#define KF_STRIDE (NU8 * 32)        // uint2 elements per kf = 448

#define SCAN_B 1024
#define NBLK   ((N_NODES + SCAN_B - 1) / SCAN_B)   // 98

// ---------------------------------------------------------------------------
// Scratch (device globals; allocation APIs are forbidden)
// ---------------------------------------------------------------------------
__device__ __align__(16) float g_h  [N_NODES * HID];
__device__ __align__(16) float g_h2 [N_NODES * HID];
__device__ __align__(16) float g_red[N_NODES * HID];
__device__ __align__(16) uint2 g_Bfrag[3 * NKF * KF_STRIDE];
// CSR scratch
__device__ int   g_cnt   [N_NODES];
__device__ int   g_rowptr[N_NODES + 1];
__device__ int   g_cur   [N_NODES];
__device__ int   g_bsum  [NBLK];
__device__ int   g_bsumex[NBLK];
__device__ __align__(16) uint2 g_edge[N_EDGES];   // {src, w bits} sorted by dst

__device__ __forceinline__ uint32_t smem_u32(const void* p) {
    uint32_t a;
    asm("{ .reg .u64 t; cvta.to.shared.u64 t, %1; cvt.u32.u64 %0, t; }" : "=r"(a) : "l"(p));
    return a;
}
__device__ __forceinline__ uint32_t h2_u32(__half2 v) {
    return *reinterpret_cast<uint32_t*>(&v);
}

#define LDSM4(r, addr)                                                           \
    asm volatile("ldmatrix.sync.aligned.m8n8.x4.shared.b16 {%0,%1,%2,%3}, [%4];" \
                 : "=r"((r)[0]), "=r"((r)[1]), "=r"((r)[2]), "=r"((r)[3])        \
                 : "r"(addr))

#define MMA16816(acc, a, bx, by)                                                 \
    asm volatile("mma.sync.aligned.m16n8k16.row.col.f32.f16.f16.f32 "            \
                 "{%0,%1,%2,%3}, {%4,%5,%6,%7}, {%8,%9}, {%0,%1,%2,%3};"         \
                 : "+f"((acc)[0]), "+f"((acc)[1]), "+f"((acc)[2]), "+f"((acc)[3])\
                 : "r"((a)[0]), "r"((a)[1]), "r"((a)[2]), "r"((a)[3]),           \
                   "r"(bx), "r"(by))

// ---------------------------------------------------------------------------
// CSR build
// ---------------------------------------------------------------------------
__global__ __launch_bounds__(256)
void hist_kernel(const int* __restrict__ dst) {
    int e = blockIdx.x * 256 + threadIdx.x;
    if (e < N_EDGES) atomicAdd(&g_cnt[dst[e]], 1);
}

__global__ __launch_bounds__(SCAN_B)
void block_sum_kernel() {
    __shared__ int s[SCAN_B];
    int i = blockIdx.x * SCAN_B + threadIdx.x;
    s[threadIdx.x] = (i < N_NODES) ? g_cnt[i] : 0;
    __syncthreads();
    for (int st = SCAN_B / 2; st > 0; st >>= 1) {
        if (threadIdx.x < st) s[threadIdx.x] += s[threadIdx.x + st];
        __syncthreads();
    }
    if (threadIdx.x == 0) g_bsum[blockIdx.x] = s[0];
}

__global__ __launch_bounds__(128)
void scan_bsum_kernel() {
    __shared__ int s[128];
    int t = threadIdx.x;
    int c = (t < NBLK) ? g_bsum[t] : 0;
    s[t] = c;
    __syncthreads();
    for (int st = 1; st < 128; st <<= 1) {
        int v = (t >= st) ? s[t - st] : 0;
        __syncthreads();
        s[t] += v;
        __syncthreads();
    }
    if (t < NBLK) g_bsumex[t] = s[t] - c;   // exclusive
}

__global__ __launch_bounds__(SCAN_B)
void rowptr_kernel() {
    __shared__ int s[SCAN_B];
    int i = blockIdx.x * SCAN_B + threadIdx.x;
    int c = (i < N_NODES) ? g_cnt[i] : 0;
    s[threadIdx.x] = c;
    __syncthreads();
    for (int st = 1; st < SCAN_B; st <<= 1) {
        int v = (threadIdx.x >= st) ? s[threadIdx.x - st] : 0;
        __syncthreads();
        s[threadIdx.x] += v;
        __syncthreads();
    }
    if (i < N_NODES) {
        int excl = g_bsumex[blockIdx.x] + s[threadIdx.x] - c;
        g_rowptr[i] = excl;
        g_cur[i]    = excl;
        if (i == N_NODES - 1) g_rowptr[N_NODES] = excl + c;
    }
}

__global__ __launch_bounds__(256)
void fill_kernel(const int* __restrict__ src, const int* __restrict__ dst,
                 const float* __restrict__ ef) {
    int e = blockIdx.x * 256 + threadIdx.x;
    if (e >= N_EDGES) return;
    int p = atomicAdd(&g_cur[dst[e]], 1);
    g_edge[p] = make_uint2((unsigned)src[e], __float_as_uint(ef[e]));
}

// ---------------------------------------------------------------------------
// Gather-reduce (CSR segment sum): red[n] = sum_e w_e * h[src_e]
// ---------------------------------------------------------------------------
__global__ __launch_bounds__(256)
void gather_kernel(const float* __restrict__ h, float* __restrict__ red) {
    const int wid  = threadIdx.x >> 5;
    const int lane = threadIdx.x & 31;
    const int n    = blockIdx.x * 8 + wid;
    if (n >= N_NODES) return;

    const int e0 = g_rowptr[n];
    const int e1 = g_rowptr[n + 1];
    float4 acc = make_float4(0.f, 0.f, 0.f, 0.f);

    int e = e0;
    for (; e + 2 <= e1; e += 2) {
        uint2 p0 = g_edge[e];
        uint2 p1 = g_edge[e + 1];
        float w0 = __uint_as_float(p0.y);
        float w1 = __uint_as_float(p1.y);
        if (lane < 25) {
            float4 v0 = *reinterpret_cast<const float4*>(h + (size_t)p0.x * HID + lane * 4);
            float4 v1 = *reinterpret_cast<const float4*>(h + (size_t)p1.x * HID + lane * 4);
            acc.x += w0 * v0.x + w1 * v1.x;
            acc.y += w0 * v0.y + w1 * v1.y;
            acc.z += w0 * v0.z + w1 * v1.z;
            acc.w += w0 * v0.w + w1 * v1.w;
        }
    }
    if (e < e1) {
        uint2 p0 = g_edge[e];
        float w0 = __uint_as_float(p0.y);
        if (lane < 25) {
            float4 v0 = *reinterpret_cast<const float4*>(h + (size_t)p0.x * HID + lane * 4);
            acc.x += w0 * v0.x; acc.y += w0 * v0.y;
            acc.z += w0 * v0.z; acc.w += w0 * v0.w;
        }
    }
    if (lane < 25)
        *reinterpret_cast<float4*>(red + (size_t)n * HID + lane * 4) = acc;
}

// ---------------------------------------------------------------------------
// Prep: pack B = fp16(W^T) into per-n8 MMA B fragments.
// Layout: [l][kf(13)][nu8(14)][lane(32)] uint2 = {b0, b1} for block nu8.
// ---------------------------------------------------------------------------
__device__ __forceinline__ __half wconvh(const float* W, int kk, int col) {
    float w = (kk < 2 * HID && col < HID) ? W[kk * HID + col] : 0.0f;
    return __float2half_rn(w);
}

__global__ __launch_bounds__(256)
void prep_B_kernel(const float* __restrict__ W1, const float* __restrict__ W2,
                   const float* __restrict__ W3)
{
    int i = blockIdx.x * 256 + threadIdx.x;
    if (i >= 3 * NKF * KF_STRIDE) return;
    int l    = i / (NKF * KF_STRIDE);
    int r    = i - l * (NKF * KF_STRIDE);
    int kf   = r / KF_STRIDE;
    int r2   = r - kf * KF_STRIDE;
    int nu8  = r2 >> 5;
    int lane = r2 & 31;

    int kk0 = kf * 16 + (lane & 3) * 2;
    int n   = nu8 * 8 + (lane >> 2);

    const float* W = (l == 0) ? W1 : (l == 1) ? W2 : W3;

    uint2 o;
    o.x = h2_u32(__half2(wconvh(W, kk0,     n), wconvh(W, kk0 + 1, n)));
    o.y = h2_u32(__half2(wconvh(W, kk0 + 8, n), wconvh(W, kk0 + 9, n)));
    g_Bfrag[i] = o;
}

// ---------------------------------------------------------------------------
// MPL GEMM: out[n,0:100] = relu( concat(h[n], red[n]) @ W + b )
// Single fp16 A x single fp16 B: 13 k16 steps x 7 n8 blocks = 91 MMAs/warp,
// balanced across all warps/SMSPs. B via LDG.64 with distance-2 register
// prefetch (prefetch after the MMA consuming bb[cur][u]); A via ldmatrix
// distance-1 prefetch. A smem 34.5KB.
// ---------------------------------------------------------------------------
__global__ __launch_bounds__(THR, 2)
void mpl_gemm_mma(const float* __restrict__ h,
                  const float* __restrict__ red,
                  const uint2* __restrict__ Bf,   // layer base in g_Bfrag
                  const float* __restrict__ b,
                  float* __restrict__ out,
                  int n_nodes)
{
    extern __shared__ __align__(16) uint8_t smem[];
    __half* sA = reinterpret_cast<__half*>(smem);
    const uint32_t sbase = smem_u32(smem);

    const int tid    = threadIdx.x;
    const int wid    = tid >> 5;
    const int lane   = tid & 31;
    const int warp_m = wid >> 1;         // 0..4
    const int warp_n = wid & 1;          // 0..1
    const int node0  = blockIdx.x * MT;

    // ---- fill A once: fp16 at [0,208) per row (zero pad 200..207) ----
    for (int i = tid; i < MT * 52; i += THR) {
        int row = i / 52;
        int kk  = (i - row * 52) * 4;
        int n   = node0 + row;
        float4 v = make_float4(0.f, 0.f, 0.f, 0.f);
        if (n < n_nodes) {
            if (kk < HID)          v = *reinterpret_cast<const float4*>(h + (size_t)n * HID + kk);
            else if (kk < 2 * HID) v = *reinterpret_cast<const float4*>(red + (size_t)n * HID + kk - HID);
        }
        __half2 h0 = __floats2half2_rn(v.x, v.y);
        __half2 h1 = __floats2half2_rn(v.z, v.w);
        *reinterpret_cast<uint2*>(sA + row * A_STR + kk) =
            make_uint2(h2_u32(h0), h2_u32(h1));
    }
    __syncthreads();

    float acc[7][4];
#pragma unroll
    for (int f = 0; f < 7; ++f)
#pragma unroll
        for (int j = 0; j < 4; ++j) acc[f][j] = 0.0f;

    const int lrow  = lane & 15;
    const int lkoff = (lane >> 4) << 3;
    const uint32_t aPtr = sbase + (uint32_t)(((warp_m * 16 + lrow) * A_STR + lkoff) * 2);
    // warp's B pointer: n8 blocks [warp_n*7 .. warp_n*7+7)
    const uint2* bp = Bf + warp_n * 7 * 32 + lane;

    uint32_t ah[2][4];
    uint2 bb[2][7];
    LDSM4(ah[0], aPtr);
#pragma unroll
    for (int u = 0; u < 7; ++u) {
        bb[0][u] = bp[u * 32];
        bb[1][u] = bp[KF_STRIDE + u * 32];
    }
#pragma unroll
    for (int k = 0; k < NKF; ++k) {
        const int cur = k & 1, nxt = cur ^ 1;
        if (k + 1 < NKF) LDSM4(ah[nxt], aPtr + (uint32_t)((k + 1) * 32));
#pragma unroll
        for (int u = 0; u < 7; ++u) {
            const uint2 bv = bb[cur][u];
            MMA16816(acc[u], ah[cur], bv.x, bv.y);
            if (k + 2 < NKF) bb[cur][u] = bp[(k + 2) * KF_STRIDE + u * 32];
        }
    }

    // ---- epilogue: bias + relu + float2 stores ----
    const int gr = lane >> 2;
    const int tc = lane & 3;
    const int r0 = node0 + warp_m * 16 + gr;
    const int r1 = r0 + 8;
#pragma unroll
    for (int f = 0; f < 7; ++f) {
        int col = warp_n * 56 + f * 8 + tc * 2;
        if (col < HID) {
            float b0 = b[col], b1 = b[col + 1];
            if (r0 < n_nodes) {
                float2 v;
                v.x = fmaxf(acc[f][0] + b0, 0.f);
                v.y = fmaxf(acc[f][1] + b1, 0.f);
                *reinterpret_cast<float2*>(out + (size_t)r0 * HID + col) = v;
            }
            if (r1 < n_nodes) {
                float2 v;
                v.x = fmaxf(acc[f][2] + b0, 0.f);
                v.y = fmaxf(acc[f][3] + b1, 0.f);
                *reinterpret_cast<float2*>(out + (size_t)r1 * HID + col) = v;
            }
        }
    }
}

// ---------------------------------------------------------------------------
// Lift GEMM (FFMA; tiny K=16): h = tanh(x @ W_lift + b_lift)
// ---------------------------------------------------------------------------
template <int KDIM>
__global__ __launch_bounds__(512, 1)
void lift_gemm_kernel(const float* __restrict__ in1,
                      const float* __restrict__ W,
                      const float* __restrict__ b,
                      float* __restrict__ out,
                      int n_nodes)
{
    extern __shared__ float sm[];
    constexpr int SSTR = KDIM + 4;
    float* sW  = sm;
    float* sIn = sm + KDIM * 128;

    const int tid   = threadIdx.x;
    const int node0 = blockIdx.x * 128;

    for (int i = tid; i < KDIM * 128; i += 512) {
        int k = i >> 7, c = i & 127;
        sW[i] = (c < HID) ? W[k * HID + c] : 0.0f;
    }
    for (int i = tid; i < 128 * KDIM; i += 512) {
        int nl = i / KDIM, k = i - nl * KDIM;
        int n  = node0 + nl;
        sIn[nl * SSTR + k] = (n < n_nodes) ? in1[n * KDIM + k] : 0.0f;
    }
    __syncthreads();

    const int lane = tid & 31;
    const int wp   = tid >> 5;
    const float* abase = sIn + wp * 8 * SSTR;
    const float* wbase = sW + lane * 4;

    float4 acc[8];
#pragma unroll
    for (int j = 0; j < 8; ++j) acc[j] = make_float4(0.f, 0.f, 0.f, 0.f);

#pragma unroll
    for (int k0 = 0; k0 < KDIM; k0 += 4) {
        const float4 w0 = *reinterpret_cast<const float4*>(wbase + (k0 + 0) * 128);
        const float4 w1 = *reinterpret_cast<const float4*>(wbase + (k0 + 1) * 128);
        const float4 w2 = *reinterpret_cast<const float4*>(wbase + (k0 + 2) * 128);
        const float4 w3 = *reinterpret_cast<const float4*>(wbase + (k0 + 3) * 128);
#pragma unroll
        for (int j = 0; j < 8; ++j) {
            const float4 a = *reinterpret_cast<const float4*>(abase + j * SSTR + k0);
            acc[j].x += a.x * w0.x; acc[j].y += a.x * w0.y; acc[j].z += a.x * w0.z; acc[j].w += a.x * w0.w;
            acc[j].x += a.y * w1.x; acc[j].y += a.y * w1.y; acc[j].z += a.y * w1.z; acc[j].w += a.y * w1.w;
            acc[j].x += a.z * w2.x; acc[j].y += a.z * w2.y; acc[j].z += a.z * w2.z; acc[j].w += a.z * w2.w;
            acc[j].x += a.w * w3.x; acc[j].y += a.w * w3.y; acc[j].z += a.w * w3.z; acc[j].w += a.w * w3.w;
        }
    }

    if (lane < 25) {
        const float4 bias = *reinterpret_cast<const float4*>(b + lane * 4);
#pragma unroll
        for (int j = 0; j < 8; ++j) {
            int n = node0 + wp * 8 + j;
            if (n < n_nodes) {
                float4 r;
                r.x = tanhf(acc[j].x + bias.x); r.y = tanhf(acc[j].y + bias.y);
                r.z = tanhf(acc[j].z + bias.z); r.w = tanhf(acc[j].w + bias.w);
                *reinterpret_cast<float4*>(out + (size_t)n * HID + lane * 4) = r;
            }
        }
    }
}

// ---------------------------------------------------------------------------
// Output head: y[n] = sigmoid(h[n,0:100] @ W_out[100x3] + b_out)
// ---------------------------------------------------------------------------
__global__ __launch_bounds__(256)
void out_kernel(const float* __restrict__ h,
                const float* __restrict__ Wo,
                const float* __restrict__ bo,
                float* __restrict__ y,
                int n_nodes)
{
    __shared__ float sW[HID * OUTF];
    int tid = threadIdx.x;
    for (int i = tid; i < HID * OUTF; i += 256) sW[i] = Wo[i];
    __syncthreads();

    int node = blockIdx.x * 256 + tid;
    if (node >= n_nodes) return;

    float a0 = bo[0], a1 = bo[1], a2 = bo[2];
    const float4* hv = reinterpret_cast<const float4*>(h + (size_t)node * HID);
#pragma unroll
    for (int kb = 0; kb < 25; ++kb) {
        float4 v = hv[kb];
        int k = kb * 4;
        a0 += v.x * sW[(k+0)*3+0]; a1 += v.x * sW[(k+0)*3+1]; a2 += v.x * sW[(k+0)*3+2];
        a0 += v.y * sW[(k+1)*3+0]; a1 += v.y * sW[(k+1)*3+1]; a2 += v.y * sW[(k+1)*3+2];
        a0 += v.z * sW[(k+2)*3+0]; a1 += v.z * sW[(k+2)*3+1]; a2 += v.z * sW[(k+2)*3+2];
        a0 += v.w * sW[(k+3)*3+0]; a1 += v.w * sW[(k+3)*3+1]; a2 += v.w * sW[(k+3)*3+2];
    }
    y[(size_t)node * 3 + 0] = 1.0f / (1.0f + expf(-a0));
    y[(size_t)node * 3 + 1] = 1.0f / (1.0f + expf(-a1));
    y[(size_t)node * 3 + 2] = 1.0f / (1.0f + expf(-a2));
}

// ---------------------------------------------------------------------------
extern "C" void kernel_launch(void* const* d_in, const int* in_sizes, int n_in,
                              void* d_out, int out_size)
{
    const float* x      = (const float*)d_in[0];
    const float* ef     = (const float*)d_in[1];
    const int*   src    = (const int*)  d_in[2];
    const int*   dst    = (const int*)  d_in[3];
    const float* W_lift = (const float*)d_in[4];
    const float* b_lift = (const float*)d_in[5];
    const float* W1     = (const float*)d_in[6];
    const float* b1     = (const float*)d_in[7];
    const float* W2     = (const float*)d_in[8];
    const float* b2     = (const float*)d_in[9];
    const float* W3     = (const float*)d_in[10];
    const float* b3     = (const float*)d_in[11];
    const float* W_out  = (const float*)d_in[12];
    const float* b_out  = (const float*)d_in[13];
    float* y = (float*)d_out;

    float *h, *h2, *red;
    uint2* Bf;
    int* cnt;
    cudaGetSymbolAddress((void**)&h,   g_h);
    cudaGetSymbolAddress((void**)&h2,  g_h2);
    cudaGetSymbolAddress((void**)&red, g_red);
    cudaGetSymbolAddress((void**)&Bf,  g_Bfrag);
    cudaGetSymbolAddress((void**)&cnt, g_cnt);

    const size_t SMEM_LIFT = (IN_F * 128 + 128 * (IN_F + 4)) * sizeof(float);

    cudaFuncSetAttribute((const void*)mpl_gemm_mma,
                         cudaFuncAttributeMaxDynamicSharedMemorySize, SA_BYTES);

    // 0) weight prep + CSR build (once per launch)
    prep_B_kernel<<<(3 * NKF * KF_STRIDE + 255) / 256, 256>>>(W1, W2, W3);
    cudaMemsetAsync(cnt, 0, N_NODES * sizeof(int));
    hist_kernel<<<(N_EDGES + 255) / 256, 256>>>(dst);
    block_sum_kernel<<<NBLK, SCAN_B>>>();
    scan_bsum_kernel<<<1, 128>>>();
    rowptr_kernel<<<NBLK, SCAN_B>>>();
    fill_kernel<<<(N_EDGES + 255) / 256, 256>>>(src, dst, ef);

    // 1) lift
    lift_gemm_kernel<IN_F><<<(N_NODES + 127) / 128, 512, SMEM_LIFT>>>(
        x, W_lift, b_lift, h, N_NODES);

    const int MPL_GRID    = (N_NODES + MT - 1) / MT;   // 1250
    const int GATHER_GRID = (N_NODES + 7) / 8;          // 12500

    const float* bs[3] = { b1, b2, b3 };
    float* bufs[4] = { h, h2, h, h2 };

    for (int l = 0; l < 3; ++l) {
        float* hin  = bufs[l];
        float* hout = bufs[l + 1];
        gather_kernel<<<GATHER_GRID, 256>>>(hin, red);
        mpl_gemm_mma<<<MPL_GRID, THR, SA_BYTES>>>(
            hin, red, Bf + (size_t)l * NKF * KF_STRIDE, bs[l], hout, N_NODES);
    }

    // 3) output head
    out_kernel<<<(N_NODES + 255) / 256, 256>>>(h2, W_out, b_out, y, N_NODES);

    (void)in_sizes; (void)n_in; (void)out_size;
}

// round 17
// speedup vs baseline: 1.4870x; 1.2174x over previous
#include <cuda_runtime.h>
#include <cuda_fp16.h>
#include <math.h>
#include <stdint.h>

#define N_NODES 100000
#define N_EDGES 1600000
#define IN_F    16
#define HID     100
#define OUTF    3

// A smem: single fp16 section [0,208), row stride 216 (432B, ldmatrix
// conflict-free: successive rows step 27 16B-units = 3 bank-groups mod 8)
#define SEC    208
#define MT     80
#define THR    320         // 10 warps: 5 along M x 2 along N
#define A_STR  216
#define SA_BYTES (MT * A_STR * 2)   // 34560

// B image (single fp16 section): [kf(13)][nu8(14 n8-blocks)][lane(32)] uint2
#define NKF    13
#define NU8    14
#define KF_STRIDE (NU8 * 32)        // uint2 elements per kf = 448

#define SCAN_B 1024
#define NBLK   ((N_NODES + SCAN_B - 1) / SCAN_B)   // 98

// ---------------------------------------------------------------------------
// Scratch (device globals; allocation APIs are forbidden). h/red kept in fp16:
// the GEMM rounds them to fp16 anyway, so only the gather input rounding is new.
// ---------------------------------------------------------------------------
__device__ __align__(16) __half g_h  [N_NODES * HID];
__device__ __align__(16) __half g_h2 [N_NODES * HID];
__device__ __align__(16) __half g_red[N_NODES * HID];
__device__ __align__(16) uint2 g_Bfrag[3 * NKF * KF_STRIDE];
// CSR scratch
__device__ int   g_cnt   [N_NODES];
__device__ int   g_rowptr[N_NODES + 1];
__device__ int   g_cur   [N_NODES];
__device__ int   g_bsum  [NBLK];
__device__ int   g_bsumex[NBLK];
__device__ __align__(16) uint2 g_edge[N_EDGES];   // {src, w bits} sorted by dst

__device__ __forceinline__ uint32_t smem_u32(const void* p) {
    uint32_t a;
    asm("{ .reg .u64 t; cvta.to.shared.u64 t, %1; cvt.u32.u64 %0, t; }" : "=r"(a) : "l"(p));
    return a;
}
__device__ __forceinline__ uint32_t h2_u32(__half2 v) {
    return *reinterpret_cast<uint32_t*>(&v);
}
__device__ __forceinline__ __half2 u32_h2(uint32_t v) {
    return *reinterpret_cast<__half2*>(&v);
}

#define LDSM4(r, addr)                                                           \
    asm volatile("ldmatrix.sync.aligned.m8n8.x4.shared.b16 {%0,%1,%2,%3}, [%4];" \
                 : "=r"((r)[0]), "=r"((r)[1]), "=r"((r)[2]), "=r"((r)[3])        \
                 : "r"(addr))

#define MMA16816(acc, a, bx, by)                                                 \
    asm volatile("mma.sync.aligned.m16n8k16.row.col.f32.f16.f16.f32 "            \
                 "{%0,%1,%2,%3}, {%4,%5,%6,%7}, {%8,%9}, {%0,%1,%2,%3};"         \
                 : "+f"((acc)[0]), "+f"((acc)[1]), "+f"((acc)[2]), "+f"((acc)[3])\
                 : "r"((a)[0]), "r"((a)[1]), "r"((a)[2]), "r"((a)[3]),           \
                   "r"(bx), "r"(by))

// ---------------------------------------------------------------------------
// CSR build
// ---------------------------------------------------------------------------
__global__ __launch_bounds__(256)
void hist_kernel(const int* __restrict__ dst) {
    int e = blockIdx.x * 256 + threadIdx.x;
    if (e < N_EDGES) atomicAdd(&g_cnt[dst[e]], 1);
}

__global__ __launch_bounds__(SCAN_B)
void block_sum_kernel() {
    __shared__ int s[SCAN_B];
    int i = blockIdx.x * SCAN_B + threadIdx.x;
    s[threadIdx.x] = (i < N_NODES) ? g_cnt[i] : 0;
    __syncthreads();
    for (int st = SCAN_B / 2; st > 0; st >>= 1) {
        if (threadIdx.x < st) s[threadIdx.x] += s[threadIdx.x + st];
        __syncthreads();
    }
    if (threadIdx.x == 0) g_bsum[blockIdx.x] = s[0];
}

__global__ __launch_bounds__(128)
void scan_bsum_kernel() {
    __shared__ int s[128];
    int t = threadIdx.x;
    int c = (t < NBLK) ? g_bsum[t] : 0;
    s[t] = c;
    __syncthreads();
    for (int st = 1; st < 128; st <<= 1) {
        int v = (t >= st) ? s[t - st] : 0;
        __syncthreads();
        s[t] += v;
        __syncthreads();
    }
    if (t < NBLK) g_bsumex[t] = s[t] - c;   // exclusive
}

__global__ __launch_bounds__(SCAN_B)
void rowptr_kernel() {
    __shared__ int s[SCAN_B];
    int i = blockIdx.x * SCAN_B + threadIdx.x;
    int c = (i < N_NODES) ? g_cnt[i] : 0;
    s[threadIdx.x] = c;
    __syncthreads();
    for (int st = 1; st < SCAN_B; st <<= 1) {
        int v = (threadIdx.x >= st) ? s[threadIdx.x - st] : 0;
        __syncthreads();
        s[threadIdx.x] += v;
        __syncthreads();
    }
    if (i < N_NODES) {
        int excl = g_bsumex[blockIdx.x] + s[threadIdx.x] - c;
        g_rowptr[i] = excl;
        g_cur[i]    = excl;
        if (i == N_NODES - 1) g_rowptr[N_NODES] = excl + c;
    }
}

__global__ __launch_bounds__(256)
void fill_kernel(const int* __restrict__ src, const int* __restrict__ dst,
                 const float* __restrict__ ef) {
    int e = blockIdx.x * 256 + threadIdx.x;
    if (e >= N_EDGES) return;
    int p = atomicAdd(&g_cur[dst[e]], 1);
    g_edge[p] = make_uint2((unsigned)src[e], __float_as_uint(ef[e]));
}

// ---------------------------------------------------------------------------
// Gather-reduce (CSR segment sum): red[n] = sum_e w_e * h[src_e]   (fp16 h)
// One warp per node; lanes 0..24 own one 4-half chunk; fp32 accumulate.
// ---------------------------------------------------------------------------
__global__ __launch_bounds__(256)
void gather_kernel(const __half* __restrict__ h, __half* __restrict__ red) {
    const int wid  = threadIdx.x >> 5;
    const int lane = threadIdx.x & 31;
    const int n    = blockIdx.x * 8 + wid;
    if (n >= N_NODES) return;

    const int e0 = g_rowptr[n];
    const int e1 = g_rowptr[n + 1];
    float4 acc = make_float4(0.f, 0.f, 0.f, 0.f);

    int e = e0;
    for (; e + 2 <= e1; e += 2) {
        uint2 p0 = g_edge[e];
        uint2 p1 = g_edge[e + 1];
        float w0 = __uint_as_float(p0.y);
        float w1 = __uint_as_float(p1.y);
        if (lane < 25) {
            uint2 r0 = *reinterpret_cast<const uint2*>(h + (size_t)p0.x * HID + lane * 4);
            uint2 r1 = *reinterpret_cast<const uint2*>(h + (size_t)p1.x * HID + lane * 4);
            float2 a0 = __half22float2(u32_h2(r0.x));
            float2 a1 = __half22float2(u32_h2(r0.y));
            float2 b0 = __half22float2(u32_h2(r1.x));
            float2 b1 = __half22float2(u32_h2(r1.y));
            acc.x += w0 * a0.x + w1 * b0.x;
            acc.y += w0 * a0.y + w1 * b0.y;
            acc.z += w0 * a1.x + w1 * b1.x;
            acc.w += w0 * a1.y + w1 * b1.y;
        }
    }
    if (e < e1) {
        uint2 p0 = g_edge[e];
        float w0 = __uint_as_float(p0.y);
        if (lane < 25) {
            uint2 r0 = *reinterpret_cast<const uint2*>(h + (size_t)p0.x * HID + lane * 4);
            float2 a0 = __half22float2(u32_h2(r0.x));
            float2 a1 = __half22float2(u32_h2(r0.y));
            acc.x += w0 * a0.x; acc.y += w0 * a0.y;
            acc.z += w0 * a1.x; acc.w += w0 * a1.y;
        }
    }
    if (lane < 25) {
        uint2 o;
        o.x = h2_u32(__floats2half2_rn(acc.x, acc.y));
        o.y = h2_u32(__floats2half2_rn(acc.z, acc.w));
        *reinterpret_cast<uint2*>(red + (size_t)n * HID + lane * 4) = o;
    }
}

// ---------------------------------------------------------------------------
// Prep: pack B = fp16(W^T) into per-n8 MMA B fragments.
// ---------------------------------------------------------------------------
__device__ __forceinline__ __half wconvh(const float* W, int kk, int col) {
    float w = (kk < 2 * HID && col < HID) ? W[kk * HID + col] : 0.0f;
    return __float2half_rn(w);
}

__global__ __launch_bounds__(256)
void prep_B_kernel(const float* __restrict__ W1, const float* __restrict__ W2,
                   const float* __restrict__ W3)
{
    int i = blockIdx.x * 256 + threadIdx.x;
    if (i >= 3 * NKF * KF_STRIDE) return;
    int l    = i / (NKF * KF_STRIDE);
    int r    = i - l * (NKF * KF_STRIDE);
    int kf   = r / KF_STRIDE;
    int r2   = r - kf * KF_STRIDE;
    int nu8  = r2 >> 5;
    int lane = r2 & 31;

    int kk0 = kf * 16 + (lane & 3) * 2;
    int n   = nu8 * 8 + (lane >> 2);

    const float* W = (l == 0) ? W1 : (l == 1) ? W2 : W3;

    uint2 o;
    o.x = h2_u32(__half2(wconvh(W, kk0,     n), wconvh(W, kk0 + 1, n)));
    o.y = h2_u32(__half2(wconvh(W, kk0 + 8, n), wconvh(W, kk0 + 9, n)));
    g_Bfrag[i] = o;
}

// ---------------------------------------------------------------------------
// MPL GEMM: out[n,0:100] = relu( concat(h[n], red[n]) @ W + b )   (all fp16 IO)
// 91 MMAs/warp. A-fill is pure uint2 copies (h/red already fp16).
// B via LDG.64 distance-2 register prefetch; A via ldmatrix distance-1.
// ---------------------------------------------------------------------------
__global__ __launch_bounds__(THR, 2)
void mpl_gemm_mma(const __half* __restrict__ h,
                  const __half* __restrict__ red,
                  const uint2* __restrict__ Bf,   // layer base in g_Bfrag
                  const float* __restrict__ b,
                  __half* __restrict__ out,
                  int n_nodes)
{
    extern __shared__ __align__(16) uint8_t smem[];
    __half* sA = reinterpret_cast<__half*>(smem);
    const uint32_t sbase = smem_u32(smem);

    const int tid    = threadIdx.x;
    const int wid    = tid >> 5;
    const int lane   = tid & 31;
    const int warp_m = wid >> 1;         // 0..4
    const int warp_n = wid & 1;          // 0..1
    const int node0  = blockIdx.x * MT;

    // ---- fill A once: direct fp16 copies; zero pad halves 200..207 ----
    for (int i = tid; i < MT * 52; i += THR) {
        int row = i / 52;
        int c4  = (i - row * 52) * 4;    // half index within row
        int n   = node0 + row;
        uint2 v = make_uint2(0u, 0u);
        if (n < n_nodes) {
            if (c4 < HID)          v = *reinterpret_cast<const uint2*>(h + (size_t)n * HID + c4);
            else if (c4 < 2 * HID) v = *reinterpret_cast<const uint2*>(red + (size_t)n * HID + c4 - HID);
        }
        *reinterpret_cast<uint2*>(sA + row * A_STR + c4) = v;
    }
    __syncthreads();

    float acc[7][4];
#pragma unroll
    for (int f = 0; f < 7; ++f)
#pragma unroll
        for (int j = 0; j < 4; ++j) acc[f][j] = 0.0f;

    const int lrow  = lane & 15;
    const int lkoff = (lane >> 4) << 3;
    const uint32_t aPtr = sbase + (uint32_t)(((warp_m * 16 + lrow) * A_STR + lkoff) * 2);
    const uint2* bp = Bf + warp_n * 7 * 32 + lane;

    uint32_t ah[2][4];
    uint2 bb[2][7];
    LDSM4(ah[0], aPtr);
#pragma unroll
    for (int u = 0; u < 7; ++u) {
        bb[0][u] = bp[u * 32];
        bb[1][u] = bp[KF_STRIDE + u * 32];
    }
#pragma unroll
    for (int k = 0; k < NKF; ++k) {
        const int cur = k & 1, nxt = cur ^ 1;
        if (k + 1 < NKF) LDSM4(ah[nxt], aPtr + (uint32_t)((k + 1) * 32));
#pragma unroll
        for (int u = 0; u < 7; ++u) {
            const uint2 bv = bb[cur][u];
            MMA16816(acc[u], ah[cur], bv.x, bv.y);
            if (k + 2 < NKF) bb[cur][u] = bp[(k + 2) * KF_STRIDE + u * 32];
        }
    }

    // ---- epilogue: bias + relu + fp16 stores ----
    const int gr = lane >> 2;
    const int tc = lane & 3;
    const int r0 = node0 + warp_m * 16 + gr;
    const int r1 = r0 + 8;
#pragma unroll
    for (int f = 0; f < 7; ++f) {
        int col = warp_n * 56 + f * 8 + tc * 2;
        if (col < HID) {
            float b0 = b[col], b1 = b[col + 1];
            if (r0 < n_nodes) {
                __half2 v = __floats2half2_rn(fmaxf(acc[f][0] + b0, 0.f),
                                              fmaxf(acc[f][1] + b1, 0.f));
                *reinterpret_cast<uint32_t*>(out + (size_t)r0 * HID + col) = h2_u32(v);
            }
            if (r1 < n_nodes) {
                __half2 v = __floats2half2_rn(fmaxf(acc[f][2] + b0, 0.f),
                                              fmaxf(acc[f][3] + b1, 0.f));
                *reinterpret_cast<uint32_t*>(out + (size_t)r1 * HID + col) = h2_u32(v);
            }
        }
    }
}

// ---------------------------------------------------------------------------
// Lift GEMM (FFMA; tiny K=16): h = tanh(x @ W_lift + b_lift) -> fp16 out
// ---------------------------------------------------------------------------
template <int KDIM>
__global__ __launch_bounds__(512, 1)
void lift_gemm_kernel(const float* __restrict__ in1,
                      const float* __restrict__ W,
                      const float* __restrict__ b,
                      __half* __restrict__ out,
                      int n_nodes)
{
    extern __shared__ float sm[];
    constexpr int SSTR = KDIM + 4;
    float* sW  = sm;
    float* sIn = sm + KDIM * 128;

    const int tid   = threadIdx.x;
    const int node0 = blockIdx.x * 128;

    for (int i = tid; i < KDIM * 128; i += 512) {
        int k = i >> 7, c = i & 127;
        sW[i] = (c < HID) ? W[k * HID + c] : 0.0f;
    }
    for (int i = tid; i < 128 * KDIM; i += 512) {
        int nl = i / KDIM, k = i - nl * KDIM;
        int n  = node0 + nl;
        sIn[nl * SSTR + k] = (n < n_nodes) ? in1[n * KDIM + k] : 0.0f;
    }
    __syncthreads();

    const int lane = tid & 31;
    const int wp   = tid >> 5;
    const float* abase = sIn + wp * 8 * SSTR;
    const float* wbase = sW + lane * 4;

    float4 acc[8];
#pragma unroll
    for (int j = 0; j < 8; ++j) acc[j] = make_float4(0.f, 0.f, 0.f, 0.f);

#pragma unroll
    for (int k0 = 0; k0 < KDIM; k0 += 4) {
        const float4 w0 = *reinterpret_cast<const float4*>(wbase + (k0 + 0) * 128);
        const float4 w1 = *reinterpret_cast<const float4*>(wbase + (k0 + 1) * 128);
        const float4 w2 = *reinterpret_cast<const float4*>(wbase + (k0 + 2) * 128);
        const float4 w3 = *reinterpret_cast<const float4*>(wbase + (k0 + 3) * 128);
#pragma unroll
        for (int j = 0; j < 8; ++j) {
            const float4 a = *reinterpret_cast<const float4*>(abase + j * SSTR + k0);
            acc[j].x += a.x * w0.x; acc[j].y += a.x * w0.y; acc[j].z += a.x * w0.z; acc[j].w += a.x * w0.w;
            acc[j].x += a.y * w1.x; acc[j].y += a.y * w1.y; acc[j].z += a.y * w1.z; acc[j].w += a.y * w1.w;
            acc[j].x += a.z * w2.x; acc[j].y += a.z * w2.y; acc[j].z += a.z * w2.z; acc[j].w += a.z * w2.w;
            acc[j].x += a.w * w3.x; acc[j].y += a.w * w3.y; acc[j].z += a.w * w3.z; acc[j].w += a.w * w3.w;
        }
    }

    if (lane < 25) {
        const float4 bias = *reinterpret_cast<const float4*>(b + lane * 4);
#pragma unroll
        for (int j = 0; j < 8; ++j) {
            int n = node0 + wp * 8 + j;
            if (n < n_nodes) {
                uint2 o;
                o.x = h2_u32(__floats2half2_rn(tanhf(acc[j].x + bias.x),
                                               tanhf(acc[j].y + bias.y)));
                o.y = h2_u32(__floats2half2_rn(tanhf(acc[j].z + bias.z),
                                               tanhf(acc[j].w + bias.w)));
                *reinterpret_cast<uint2*>(out + (size_t)n * HID + lane * 4) = o;
            }
        }
    }
}

// ---------------------------------------------------------------------------
// Output head: y[n] = sigmoid(h[n,0:100] @ W_out[100x3] + b_out)   (fp16 h)
// ---------------------------------------------------------------------------
__global__ __launch_bounds__(256)
void out_kernel(const __half* __restrict__ h,
                const float* __restrict__ Wo,
                const float* __restrict__ bo,
                float* __restrict__ y,
                int n_nodes)
{
    __shared__ float sW[HID * OUTF];
    int tid = threadIdx.x;
    for (int i = tid; i < HID * OUTF; i += 256) sW[i] = Wo[i];
    __syncthreads();

    int node = blockIdx.x * 256 + tid;
    if (node >= n_nodes) return;

    float a0 = bo[0], a1 = bo[1], a2 = bo[2];
    const uint2* hv = reinterpret_cast<const uint2*>(h + (size_t)node * HID);
#pragma unroll
    for (int kb = 0; kb < 25; ++kb) {
        uint2 r = hv[kb];
        float2 v0 = __half22float2(u32_h2(r.x));
        float2 v1 = __half22float2(u32_h2(r.y));
        int k = kb * 4;
        a0 += v0.x * sW[(k+0)*3+0]; a1 += v0.x * sW[(k+0)*3+1]; a2 += v0.x * sW[(k+0)*3+2];
        a0 += v0.y * sW[(k+1)*3+0]; a1 += v0.y * sW[(k+1)*3+1]; a2 += v0.y * sW[(k+1)*3+2];
        a0 += v1.x * sW[(k+2)*3+0]; a1 += v1.x * sW[(k+2)*3+1]; a2 += v1.x * sW[(k+2)*3+2];
        a0 += v1.y * sW[(k+3)*3+0]; a1 += v1.y * sW[(k+3)*3+1]; a2 += v1.y * sW[(k+3)*3+2];
    }
    y[(size_t)node * 3 + 0] = 1.0f / (1.0f + expf(-a0));
    y[(size_t)node * 3 + 1] = 1.0f / (1.0f + expf(-a1));
    y[(size_t)node * 3 + 2] = 1.0f / (1.0f + expf(-a2));
}

// ---------------------------------------------------------------------------
extern "C" void kernel_launch(void* const* d_in, const int* in_sizes, int n_in,
                              void* d_out, int out_size)
{
    const float* x      = (const float*)d_in[0];
    const float* ef     = (const float*)d_in[1];
    const int*   src    = (const int*)  d_in[2];
    const int*   dst    = (const int*)  d_in[3];
    const float* W_lift = (const float*)d_in[4];
    const float* b_lift = (const float*)d_in[5];
    const float* W1     = (const float*)d_in[6];
    const float* b1     = (const float*)d_in[7];
    const float* W2     = (const float*)d_in[8];
    const float* b2     = (const float*)d_in[9];
    const float* W3     = (const float*)d_in[10];
    const float* b3     = (const float*)d_in[11];
    const float* W_out  = (const float*)d_in[12];
    const float* b_out  = (const float*)d_in[13];
    float* y = (float*)d_out;

    __half *h, *h2, *red;
    uint2* Bf;
    int* cnt;
    cudaGetSymbolAddress((void**)&h,   g_h);
    cudaGetSymbolAddress((void**)&h2,  g_h2);
    cudaGetSymbolAddress((void**)&red, g_red);
    cudaGetSymbolAddress((void**)&Bf,  g_Bfrag);
    cudaGetSymbolAddress((void**)&cnt, g_cnt);

    const size_t SMEM_LIFT = (IN_F * 128 + 128 * (IN_F + 4)) * sizeof(float);

    cudaFuncSetAttribute((const void*)mpl_gemm_mma,
                         cudaFuncAttributeMaxDynamicSharedMemorySize, SA_BYTES);

    // 0) weight prep + CSR build (once per launch)
    prep_B_kernel<<<(3 * NKF * KF_STRIDE + 255) / 256, 256>>>(W1, W2, W3);
    cudaMemsetAsync(cnt, 0, N_NODES * sizeof(int));
    hist_kernel<<<(N_EDGES + 255) / 256, 256>>>(dst);
    block_sum_kernel<<<NBLK, SCAN_B>>>();
    scan_bsum_kernel<<<1, 128>>>();
    rowptr_kernel<<<NBLK, SCAN_B>>>();
    fill_kernel<<<(N_EDGES + 255) / 256, 256>>>(src, dst, ef);

    // 1) lift
    lift_gemm_kernel<IN_F><<<(N_NODES + 127) / 128, 512, SMEM_LIFT>>>(
        x, W_lift, b_lift, h, N_NODES);

    const int MPL_GRID    = (N_NODES + MT - 1) / MT;   // 1250
    const int GATHER_GRID = (N_NODES + 7) / 8;          // 12500

    const float* bs[3] = { b1, b2, b3 };
    __half* bufs[4] = { h, h2, h, h2 };

    for (int l = 0; l < 3; ++l) {
        __half* hin  = bufs[l];
        __half* hout = bufs[l + 1];
        gather_kernel<<<GATHER_GRID, 256>>>(hin, red);
        mpl_gemm_mma<<<MPL_GRID, THR, SA_BYTES>>>(
            hin, red, Bf + (size_t)l * NKF * KF_STRIDE, bs[l], hout, N_NODES);
    }

    // 3) output head
    out_kernel<<<(N_NODES + 255) / 256, 256>>>(h2, W_out, b_out, y, N_NODES);

    (void)in_sizes; (void)n_in; (void)out_size;
}